// round 11
// baseline (speedup 1.0000x reference)
#include <cuda_runtime.h>
#include <cuda_fp16.h>
#include <math.h>
#include <stdint.h>

// ---------------- problem constants ----------------
#define B_SZ   512
#define SEQ    102
#define EMB    256
#define NH     16
#define HD     16
#define FFD    1024
#define NLAYER 3
#define KSZ    50
#define PSZ    1000
#define MTOK   (B_SZ*SEQ)      // 52224 tokens
#define OUTW   ((PSZ+1)*2)     // 2002
#define QKVW   (3*EMB)         // 768

typedef unsigned long long ull;

// ---------------- device scratch (static; no allocs allowed) ----------------
__device__ float  g_X   [MTOK*EMB];
__device__ float  g_X1  [MTOK*EMB];
__device__ __half g_QKVh[MTOK*QKVW];
__device__ __half g_Xh  [MTOK*EMB];
__device__ __half g_Oh  [MTOK*EMB];
__device__ __half g_X1h [MTOK*EMB];
__device__ __half g_Hh  [MTOK*FFD];
#define WQKV_SZ (QKVW*EMB)
#define WC_SZ   (EMB*EMB)
#define W1_SZ   (FFD*EMB)
#define W2_SZ   (EMB*FFD)
#define WL_SZ   (WQKV_SZ + WC_SZ + W1_SZ + W2_SZ)
__device__ __half g_Wh[NLAYER*WL_SZ];

// ---------------- helpers ----------------
__device__ __forceinline__ uint32_t smem_u32(const void* p) {
    uint32_t a;
    asm("{ .reg .u64 t; cvta.to.shared.u64 t, %1; cvt.u32.u64 %0, t; }"
        : "=r"(a) : "l"(p));
    return a;
}
__device__ __forceinline__ void cp16(uint32_t dst, const void* src) {
    asm volatile("cp.async.cg.shared.global [%0], [%1], 16;" :: "r"(dst), "l"(src));
}
#define CP_COMMIT() asm volatile("cp.async.commit_group;" ::: "memory")
#define CP_WAIT2()  asm volatile("cp.async.wait_group 2;" ::: "memory")

#define LDSM4(r, addr) \
    asm volatile("ldmatrix.sync.aligned.m8n8.x4.shared.b16 {%0,%1,%2,%3}, [%4];" \
        : "=r"((r)[0]), "=r"((r)[1]), "=r"((r)[2]), "=r"((r)[3]) : "r"(addr))

#define MMA16816(d, a, b) \
    asm volatile("mma.sync.aligned.m16n8k16.row.col.f32.f16.f16.f32 " \
        "{%0,%1,%2,%3}, {%4,%5,%6,%7}, {%8,%9}, {%0,%1,%2,%3};" \
        : "+f"((d)[0]), "+f"((d)[1]), "+f"((d)[2]), "+f"((d)[3]) \
        : "r"((a)[0]), "r"((a)[1]), "r"((a)[2]), "r"((a)[3]), \
          "r"((b)[0]), "r"((b)[1]))

// packed f32x2
__device__ __forceinline__ ull pack2(float a, float b) {
    ull r; asm("mov.b64 %0, {%1, %2};" : "=l"(r) : "f"(a), "f"(b)); return r;
}
__device__ __forceinline__ ull pdup(float a) {
    ull r; asm("mov.b64 %0, {%1, %1};" : "=l"(r) : "f"(a)); return r;
}
__device__ __forceinline__ float2 unpk2(ull v) {
    float2 f; asm("mov.b64 {%0, %1}, %2;" : "=f"(f.x), "=f"(f.y) : "l"(v)); return f;
}
__device__ __forceinline__ ull ffma2(ull a, ull b, ull c) {
    ull d; asm("fma.rn.f32x2 %0, %1, %2, %3;" : "=l"(d) : "l"(a), "l"(b), "l"(c)); return d;
}

// ---------------- weight convert ----------------
__global__ void wconv4_kernel(const float* __restrict__ Wq, const float* __restrict__ Wk,
                              const float* __restrict__ Wv, const float* __restrict__ Wc,
                              __half* __restrict__ oh)
{
    int l   = blockIdx.z;
    int mat = blockIdx.y >> 3;
    int kt  = blockIdx.y & 7;
    const float* W = (mat == 0) ? Wq : (mat == 1) ? Wk : (mat == 2) ? Wv : Wc;
    W  += (size_t)l*EMB*EMB;
    __half* dst = oh + (size_t)l*WL_SZ + (size_t)mat*EMB*EMB;

    __shared__ float tile[32][33];
    int n0 = blockIdx.x*32, k0 = kt*32;
    int tx = threadIdx.x, ty = threadIdx.y;  // 32 x 8
    #pragma unroll
    for (int i = ty; i < 32; i += 8)
        tile[i][tx] = W[(size_t)(k0+i)*EMB + n0 + tx];
    __syncthreads();
    #pragma unroll
    for (int i = ty; i < 32; i += 8)
        dst[(size_t)(n0+i)*EMB + k0 + tx] = __float2half_rn(tile[tx][i]);
}

__global__ void wconv_kernel(const float* __restrict__ W,
                             __half* __restrict__ oh,
                             int K, int N, size_t wstride, size_t ostride)
{
    int l = blockIdx.z;
    W  += (size_t)l*wstride;
    oh += (size_t)l*ostride;
    __shared__ float tile[32][33];
    int n0 = blockIdx.x*32, k0 = blockIdx.y*32;
    int tx = threadIdx.x, ty = threadIdx.y;  // 32 x 8
    #pragma unroll
    for (int i = ty; i < 32; i += 8)
        tile[i][tx] = W[(size_t)(k0+i)*N + n0 + tx];
    __syncthreads();
    #pragma unroll
    for (int i = ty; i < 32; i += 8)
        oh[(size_t)(n0+i)*K + k0 + tx] = __float2half_rn(tile[tx][i]);
}

// ---------------- build initial sequence: one block per batch ----------------
__global__ __launch_bounds__(256) void build_kernel(
    const float* __restrict__ x,
    const float* __restrict__ Wnv, const float* __restrict__ bnv,
    const float* __restrict__ Wv,  const float* __restrict__ bv,
    float* __restrict__ X, __half* __restrict__ Xh)
{
    int b = blockIdx.x, t = threadIdx.x;
    __shared__ float xs0[EMB], xs1[EMB];
    const float* xb  = x  + (size_t)b*SEQ*EMB;
    float* Xb        = X  + (size_t)b*SEQ*EMB;
    __half* Xhb      = Xh + (size_t)b*SEQ*EMB;

    xs0[t] = xb[(size_t)50*EMB + t];
    xs1[t] = xb[(size_t)101*EMB + t];
    __syncthreads();

    // two GEMVs: out0 = xs0@Wnv + bnv ; out51 = xs1@Wv + bv
    float a0 = bnv[t], a1 = bv[t];
    #pragma unroll 8
    for (int k = 0; k < EMB; k++) {
        a0 = fmaf(xs0[k], Wnv[k*EMB + t], a0);
        a1 = fmaf(xs1[k], Wv[k*EMB + t], a1);
    }
    Xb[t] = a0;                 Xhb[t] = __float2half_rn(a0);
    Xb[(size_t)51*EMB + t] = a1; Xhb[(size_t)51*EMB + t] = __float2half_rn(a1);

    // copies: dst 1..50 <- src 0..49 ; dst 52..101 <- src 51..100
    for (int idx = t; idx < 100*(EMB/4); idx += 256) {
        int row = idx >> 6;                 // 0..99
        int c4  = (idx & 63) << 2;
        int srcrow = (row < 50) ? row : row + 1;
        int dstrow = srcrow + 1;
        float4 v = *(const float4*)(xb + (size_t)srcrow*EMB + c4);
        *(float4*)(Xb + (size_t)dstrow*EMB + c4) = v;
        *(__half2*)(Xhb + (size_t)dstrow*EMB + c4) =
            __halves2half2(__float2half_rn(v.x), __float2half_rn(v.y));
        *(__half2*)(Xhb + (size_t)dstrow*EMB + c4 + 2) =
            __halves2half2(__float2half_rn(v.z), __float2half_rn(v.w));
    }
}

// ================= HMMA fp16 GEMM, 128x128 tile, 4-stage cp.async =================
#define PITCH 40
#define A_ST  (128*PITCH)
#define B_ST  (128*PITCH)
#define NSTG  4
#define AB0   (NSTG*A_ST*2)
#define GEMM_SMEM (NSTG*(A_ST + B_ST)*2)  // 81920 bytes

__global__ __launch_bounds__(256, 2) void gemm_mma(
    const __half* __restrict__ Ah, const __half* __restrict__ Bh,
    const float* __restrict__ bias, const float* __restrict__ res,
    float* __restrict__ C, __half* __restrict__ Ch,
    int M, int N, int K, int do_relu)
{
    extern __shared__ __align__(16) __half sm[];
    const uint32_t uBase = smem_u32(sm);

    const int t    = threadIdx.x;
    const int lane = t & 31;
    const int wid  = t >> 5;
    const int wm   = wid & 3;
    const int wn   = wid >> 2;
    const int bm   = blockIdx.y * 128;
    const int bn   = blockIdx.x * 128;

    float acc[2][8][4];
    #pragma unroll
    for (int mt = 0; mt < 2; mt++)
        #pragma unroll
        for (int nt = 0; nt < 8; nt++)
            #pragma unroll
            for (int i = 0; i < 4; i++) acc[mt][nt][i] = 0.f;

    const int nchunks = K >> 5;

    auto load_stage = [&](int ck) {
        const int s  = ck % NSTG;
        const int k0 = ck << 5;
        #pragma unroll
        for (int i = 0; i < 2; i++) {
            int cid = t + i*256;
            int row = cid >> 2;
            int c8  = (cid & 3) << 3;
            cp16(uBase + (uint32_t)((s*128 + row)*PITCH + c8)*2,
                 Ah + (size_t)(bm + row)*K + k0 + c8);
        }
        #pragma unroll
        for (int i = 0; i < 2; i++) {
            int cid = t + i*256;
            int row = cid >> 2;
            int c8  = (cid & 3) << 3;
            cp16(uBase + AB0 + (uint32_t)((s*128 + row)*PITCH + c8)*2,
                 Bh + (size_t)(bn + row)*K + k0 + c8);
        }
    };

    load_stage(0); CP_COMMIT();
    if (nchunks > 1) { load_stage(1); CP_COMMIT(); }
    if (nchunks > 2) { load_stage(2); CP_COMMIT(); }

    for (int ck = 0; ck < nchunks; ck++) {
        CP_WAIT2();
        __syncthreads();
        if (ck + 3 < nchunks) { load_stage(ck + 3); CP_COMMIT(); }
        else { CP_COMMIT(); }

        const int s = ck % NSTG;
        const uint32_t aBase = uBase + (uint32_t)(s*A_ST)*2;
        const uint32_t bBase = uBase + AB0 + (uint32_t)(s*B_ST)*2;

        #pragma unroll
        for (int ks = 0; ks < 2; ks++) {
            uint32_t ah[2][4], bh[8][2];
            const int kcol = ks*16 + ((lane >> 4) << 3);
            #pragma unroll
            for (int mt = 0; mt < 2; mt++) {
                int row = wm*32 + mt*16 + (lane & 15);
                LDSM4(ah[mt], aBase + (uint32_t)(row*PITCH + kcol)*2);
            }
            #pragma unroll
            for (int p = 0; p < 4; p++) {
                int row = wn*64 + p*16 + (lane & 15);
                uint32_t r4[4];
                LDSM4(r4, bBase + (uint32_t)(row*PITCH + kcol)*2);
                bh[2*p][0] = r4[0]; bh[2*p+1][0] = r4[1];
                bh[2*p][1] = r4[2]; bh[2*p+1][1] = r4[3];
            }
            #pragma unroll
            for (int mt = 0; mt < 2; mt++)
                #pragma unroll
                for (int nt = 0; nt < 8; nt++)
                    MMA16816(acc[mt][nt], ah[mt], bh[nt]);
        }
    }

    // ---- epilogue ----
    const int rb = bm + wm*32;
    const int cb = bn + wn*64;
    const int lr = lane >> 2;
    const int lc = (lane & 3) << 1;
    #pragma unroll
    for (int mt = 0; mt < 2; mt++) {
        #pragma unroll
        for (int nt = 0; nt < 8; nt++) {
            int r0 = rb + mt*16 + lr;
            int r1 = r0 + 8;
            int cc = cb + nt*8 + lc;
            float2 v0 = make_float2(acc[mt][nt][0], acc[mt][nt][1]);
            float2 v1 = make_float2(acc[mt][nt][2], acc[mt][nt][3]);
            if (bias) {
                float2 bb = *(const float2*)(bias + cc);
                v0.x += bb.x; v0.y += bb.y; v1.x += bb.x; v1.y += bb.y;
            }
            if (res) {
                float2 q0 = *(const float2*)(res + (size_t)r0*N + cc);
                float2 q1 = *(const float2*)(res + (size_t)r1*N + cc);
                v0.x += q0.x; v0.y += q0.y; v1.x += q1.x; v1.y += q1.y;
            }
            if (do_relu) {
                v0.x = fmaxf(v0.x, 0.f); v0.y = fmaxf(v0.y, 0.f);
                v1.x = fmaxf(v1.x, 0.f); v1.y = fmaxf(v1.y, 0.f);
            }
            if (C) {
                *(float2*)(C + (size_t)r0*N + cc) = v0;
                *(float2*)(C + (size_t)r1*N + cc) = v1;
            }
            if (Ch) {
                *(__half2*)(Ch + (size_t)r0*N + cc) =
                    __halves2half2(__float2half_rn(v0.x), __float2half_rn(v0.y));
                *(__half2*)(Ch + (size_t)r1*N + cc) =
                    __halves2half2(__float2half_rn(v1.x), __float2half_rn(v1.y));
            }
        }
    }
}

// ---------------- attention: two-phase, scores in REGISTERS ----------------
__global__ __launch_bounds__(128) void attn_kernel(
    const __half* __restrict__ QKV, __half* __restrict__ Oh)
{
    int b = blockIdx.x, h = blockIdx.y, t = threadIdx.x;  // 128 threads
    __shared__ __align__(16) float Ks[SEQ][HD];
    __shared__ __align__(16) float Vs[SEQ][HD];
    size_t rowb = (size_t)b*SEQ*QKVW;
    int hc = h*HD;
    for (int idx = t; idx < SEQ*(HD/2); idx += 128) {
        int n = idx >> 3;
        int j = (idx & 7) << 1;
        float2 kf = __half22float2(*(const __half2*)(QKV + rowb + (size_t)n*QKVW + EMB   + hc + j));
        float2 vf = __half22float2(*(const __half2*)(QKV + rowb + (size_t)n*QKVW + 2*EMB + hc + j));
        Ks[n][j] = kf.x; Ks[n][j+1] = kf.y;
        Vs[n][j] = vf.x; Vs[n][j+1] = vf.y;
    }
    __syncthreads();
    if (t < SEQ) {
        ull q2[8];
        {
            const __half2* qr = (const __half2*)(QKV + rowb + (size_t)t*QKVW + hc);
            #pragma unroll
            for (int j = 0; j < 8; j++) {
                float2 qf = __half22float2(qr[j]);
                q2[j] = pack2(qf.x*0.25f, qf.y*0.25f);   // 1/sqrt(16)
            }
        }
        // phase 1: all scores (regs) + max
        float mx = -1e30f;
        __half2 sc[SEQ/2];
        #pragma unroll
        for (int mm = 0; mm < SEQ/2; mm++) {
            const ull* ka = (const ull*)&Ks[2*mm][0];
            const ull* kb = (const ull*)&Ks[2*mm+1][0];
            ull sa = pdup(0.f), sb = pdup(0.f);
            #pragma unroll
            for (int j = 0; j < 8; j++) {
                sa = ffma2(q2[j], ka[j], sa);
                sb = ffma2(q2[j], kb[j], sb);
            }
            float2 fa = unpk2(sa), fb = unpk2(sb);
            float s0 = fa.x + fa.y, s1 = fb.x + fb.y;
            mx = fmaxf(mx, fmaxf(s0, s1));
            sc[mm] = __halves2half2(__float2half_rn(s0), __float2half_rn(s1));
        }
        // phase 2: exp + weighted sum (no rescale)
        float l = 0.f;
        ull o2[8];
        #pragma unroll
        for (int j = 0; j < 8; j++) o2[j] = pdup(0.f);
        #pragma unroll
        for (int mm = 0; mm < SEQ/2; mm++) {
            float2 s = __half22float2(sc[mm]);
            float e0 = __expf(s.x - mx);
            float e1 = __expf(s.y - mx);
            l += e0 + e1;
            ull e02 = pdup(e0), e12 = pdup(e1);
            const ull* va = (const ull*)&Vs[2*mm][0];
            const ull* vb = (const ull*)&Vs[2*mm+1][0];
            #pragma unroll
            for (int j = 0; j < 8; j++) {
                o2[j] = ffma2(e02, va[j], o2[j]);
                o2[j] = ffma2(e12, vb[j], o2[j]);
            }
        }
        float inv = 1.f / l;
        size_t ob = ((size_t)b*SEQ + t)*EMB + hc;
        #pragma unroll
        for (int j = 0; j < 8; j++) {
            float2 ov = unpk2(o2[j]);
            *(__half2*)(Oh + ob + 2*j) =
                __halves2half2(__float2half_rn(ov.x*inv), __float2half_rn(ov.y*inv));
        }
    }
}

// ---------------- final: logits -> masked softmax -> props -> scatter ----------------
__global__ __launch_bounds__(128) void final_kernel(
    const float* __restrict__ X,  const float* __restrict__ Wf,
    const float* __restrict__ bf, const float* __restrict__ mask,
    const int* __restrict__ lastu, const int* __restrict__ depotu,
    float* __restrict__ out)
{
    int b = blockIdx.x, t = threadIdx.x;   // 128 threads
    __shared__ float lg[128];
    __shared__ float red[128];

    float acc = -INFINITY;
    if (t < SEQ) {
        const float4* r4 = (const float4*)(X + ((size_t)b*SEQ + t)*EMB);
        const float4* w4 = (const float4*)Wf;
        float s = bf[0];
        #pragma unroll 16
        for (int k = 0; k < EMB/4; k++) {
            float4 a = r4[k], w = w4[k];
            s = fmaf(a.x, w.x, s); s = fmaf(a.y, w.y, s);
            s = fmaf(a.z, w.z, s); s = fmaf(a.w, w.w, s);
        }
        if (t >= 1 && t <= KSZ) s += mask[(size_t)b*KSZ + (t-1)];
        if (t == 0 || t == KSZ+1) s = -INFINITY;
        acc = s;
    }
    lg[t] = acc;
    __syncthreads();

    red[t] = lg[t];
    __syncthreads();
    #pragma unroll
    for (int s = 64; s > 0; s >>= 1) {
        if (t < s) red[t] = fmaxf(red[t], red[t+s]);
        __syncthreads();
    }
    float mx = red[0];
    __syncthreads();

    float e = 0.f;
    if (t < SEQ && t != 0 && t != KSZ+1) e = __expf(lg[t] - mx);
    red[t] = e;
    __syncthreads();
    #pragma unroll
    for (int s = 64; s > 0; s >>= 1) {
        if (t < s) red[t] += red[t+s];
        __syncthreads();
    }
    float inv = 1.f / red[0];
    __syncthreads();
    lg[t] = e * inv;
    __syncthreads();

    float* orow = out + (size_t)b*OUTW;
    for (int i = t; i < OUTW; i += 128) orow[i] = 1e-20f;
    __syncthreads();

    if (t < KSZ) {
        float p1 = lg[1 + t];
        float p2 = lg[KSZ + 2 + t];
        if (p1 <= 1e-5f) p1 += 1e-7f;
        if (p2 <= 1e-5f) p2 += 1e-7f;
        orow[lastu[(size_t)b*KSZ + t]] = p1;
        orow[(PSZ + 1) + depotu[(size_t)b*KSZ + t]] = p2;
    }
}

// ---------------- launch ----------------
extern "C" void kernel_launch(void* const* d_in, const int* in_sizes, int n_in,
                              void* d_out, int out_size)
{
    (void)in_sizes; (void)n_in; (void)out_size;
    const float* x    = (const float*)d_in[0];
    const float* mask = (const float*)d_in[1];
    const float* Wnv  = (const float*)d_in[2];
    const float* bnv  = (const float*)d_in[3];
    const float* Wv_  = (const float*)d_in[4];
    const float* bv   = (const float*)d_in[5];
    const float* Wq   = (const float*)d_in[6];
    const float* Wk   = (const float*)d_in[7];
    const float* Wvp  = (const float*)d_in[8];
    const float* Wc   = (const float*)d_in[9];
    const float* bc   = (const float*)d_in[10];
    const float* W1   = (const float*)d_in[11];
    const float* b1   = (const float*)d_in[12];
    const float* W2   = (const float*)d_in[13];
    const float* b2   = (const float*)d_in[14];
    const float* Wf   = (const float*)d_in[15];
    const float* bf   = (const float*)d_in[16];
    const int*  lastu = (const int*)d_in[17];
    const int* depotu = (const int*)d_in[18];

    float *X, *X1;
    __half *QKVh, *Xh, *Oh, *X1h, *Hh, *Wh;
    cudaGetSymbolAddress((void**)&X,    g_X);
    cudaGetSymbolAddress((void**)&X1,   g_X1);
    cudaGetSymbolAddress((void**)&QKVh, g_QKVh);
    cudaGetSymbolAddress((void**)&Xh,   g_Xh);
    cudaGetSymbolAddress((void**)&Oh,   g_Oh);
    cudaGetSymbolAddress((void**)&X1h,  g_X1h);
    cudaGetSymbolAddress((void**)&Hh,   g_Hh);
    cudaGetSymbolAddress((void**)&Wh,   g_Wh);

    cudaFuncSetAttribute(gemm_mma, cudaFuncAttributeMaxDynamicSharedMemorySize,
                         GEMM_SMEM);

    dim3 ct(32, 8);
    dim3 gQKV(QKVW/128, MTOK/128);   // (6, 408)
    dim3 gE  (EMB/128,  MTOK/128);   // (2, 408)
    dim3 gF  (FFD/128,  MTOK/128);   // (8, 408)

    wconv4_kernel<<<dim3(EMB/32, 4*(EMB/32), NLAYER), ct>>>(Wq, Wk, Wvp, Wc, Wh);
    wconv_kernel<<<dim3(FFD/32, EMB/32, NLAYER), ct>>>(W1, Wh + WQKV_SZ + WC_SZ, EMB, FFD, (size_t)EMB*FFD, WL_SZ);
    wconv_kernel<<<dim3(EMB/32, FFD/32, NLAYER), ct>>>(W2, Wh + WQKV_SZ + WC_SZ + W1_SZ, FFD, EMB, (size_t)FFD*EMB, WL_SZ);

    build_kernel<<<B_SZ, 256>>>(x, Wnv, bnv, Wv_, bv, X, Xh);

    for (int l = 0; l < NLAYER; l++) {
        const __half* wh   = Wh + (size_t)l*WL_SZ;
        const __half* wc_h = wh + WQKV_SZ;
        const __half* w1_h = wh + WQKV_SZ + WC_SZ;
        const __half* w2_h = wh + WQKV_SZ + WC_SZ + W1_SZ;
        const float* bcl = bc + (size_t)l*EMB;
        const float* b1l = b1 + (size_t)l*FFD;
        const float* b2l = b2 + (size_t)l*EMB;

        gemm_mma<<<gQKV, 256, GEMM_SMEM>>>(Xh, wh, nullptr, nullptr,
                                           nullptr, QKVh, MTOK, QKVW, EMB, 0);
        attn_kernel<<<dim3(B_SZ, NH), 128>>>(QKVh, Oh);
        gemm_mma<<<gE, 256, GEMM_SMEM>>>(Oh, wc_h, bcl, X,
                                         X1, X1h, MTOK, EMB, EMB, 0);
        gemm_mma<<<gF, 256, GEMM_SMEM>>>(X1h, w1_h, b1l, nullptr,
                                         nullptr, Hh, MTOK, FFD, EMB, 1);
        gemm_mma<<<gE, 256, GEMM_SMEM>>>(Hh, w2_h, b2l, X1,
                                         X, Xh, MTOK, EMB, FFD, 0);
    }

    final_kernel<<<B_SZ, 128>>>(X, Wf, bf, mask, lastu, depotu, (float*)d_out);
}

// round 12
// speedup vs baseline: 1.3240x; 1.3240x over previous
#include <cuda_runtime.h>
#include <cuda_fp16.h>
#include <math.h>
#include <stdint.h>

// ---------------- problem constants ----------------
#define B_SZ   512
#define SEQ    102
#define EMB    256
#define NH     16
#define HD     16
#define FFD    1024
#define NLAYER 3
#define KSZ    50
#define PSZ    1000
#define MTOK   (B_SZ*SEQ)      // 52224 tokens
#define OUTW   ((PSZ+1)*2)     // 2002
#define QKVW   (3*EMB)         // 768

typedef unsigned long long ull;

// ---------------- device scratch (static; no allocs allowed) ----------------
__device__ float  g_X   [MTOK*EMB];
__device__ float  g_X1  [MTOK*EMB];
__device__ __half g_QKVh[MTOK*QKVW];
__device__ __half g_Xh  [MTOK*EMB];
__device__ __half g_Oh  [MTOK*EMB];
__device__ __half g_X1h [MTOK*EMB];
__device__ __half g_Hh  [MTOK*FFD];
#define WQKV_SZ (QKVW*EMB)
#define WC_SZ   (EMB*EMB)
#define W1_SZ   (FFD*EMB)
#define W2_SZ   (EMB*FFD)
#define WL_SZ   (WQKV_SZ + WC_SZ + W1_SZ + W2_SZ)
__device__ __half g_Wh[NLAYER*WL_SZ];

// ---------------- helpers ----------------
__device__ __forceinline__ uint32_t smem_u32(const void* p) {
    uint32_t a;
    asm("{ .reg .u64 t; cvta.to.shared.u64 t, %1; cvt.u32.u64 %0, t; }"
        : "=r"(a) : "l"(p));
    return a;
}
__device__ __forceinline__ void cp16(uint32_t dst, const void* src) {
    asm volatile("cp.async.cg.shared.global [%0], [%1], 16;" :: "r"(dst), "l"(src));
}
#define CP_COMMIT() asm volatile("cp.async.commit_group;" ::: "memory")
#define CP_WAIT2()  asm volatile("cp.async.wait_group 2;" ::: "memory")

#define LDSM4(r, addr) \
    asm volatile("ldmatrix.sync.aligned.m8n8.x4.shared.b16 {%0,%1,%2,%3}, [%4];" \
        : "=r"((r)[0]), "=r"((r)[1]), "=r"((r)[2]), "=r"((r)[3]) : "r"(addr))

#define LDSM4T(r, addr) \
    asm volatile("ldmatrix.sync.aligned.m8n8.x4.trans.shared.b16 {%0,%1,%2,%3}, [%4];" \
        : "=r"((r)[0]), "=r"((r)[1]), "=r"((r)[2]), "=r"((r)[3]) : "r"(addr))

#define MMA16816(d, a, b) \
    asm volatile("mma.sync.aligned.m16n8k16.row.col.f32.f16.f16.f32 " \
        "{%0,%1,%2,%3}, {%4,%5,%6,%7}, {%8,%9}, {%0,%1,%2,%3};" \
        : "+f"((d)[0]), "+f"((d)[1]), "+f"((d)[2]), "+f"((d)[3]) \
        : "r"((a)[0]), "r"((a)[1]), "r"((a)[2]), "r"((a)[3]), \
          "r"((b)[0]), "r"((b)[1]))

__device__ __forceinline__ uint32_t pack_h2(float a, float b) {
    __half2 h = __floats2half2_rn(a, b);
    return *(uint32_t*)&h;
}

// ---------------- weight convert ----------------
__global__ void wconv4_kernel(const float* __restrict__ Wq, const float* __restrict__ Wk,
                              const float* __restrict__ Wv, const float* __restrict__ Wc,
                              __half* __restrict__ oh)
{
    int l   = blockIdx.z;
    int mat = blockIdx.y >> 3;
    int kt  = blockIdx.y & 7;
    const float* W = (mat == 0) ? Wq : (mat == 1) ? Wk : (mat == 2) ? Wv : Wc;
    W  += (size_t)l*EMB*EMB;
    __half* dst = oh + (size_t)l*WL_SZ + (size_t)mat*EMB*EMB;

    __shared__ float tile[32][33];
    int n0 = blockIdx.x*32, k0 = kt*32;
    int tx = threadIdx.x, ty = threadIdx.y;  // 32 x 8
    #pragma unroll
    for (int i = ty; i < 32; i += 8)
        tile[i][tx] = W[(size_t)(k0+i)*EMB + n0 + tx];
    __syncthreads();
    #pragma unroll
    for (int i = ty; i < 32; i += 8)
        dst[(size_t)(n0+i)*EMB + k0 + tx] = __float2half_rn(tile[tx][i]);
}

__global__ void wconv_kernel(const float* __restrict__ W,
                             __half* __restrict__ oh,
                             int K, int N, size_t wstride, size_t ostride)
{
    int l = blockIdx.z;
    W  += (size_t)l*wstride;
    oh += (size_t)l*ostride;
    __shared__ float tile[32][33];
    int n0 = blockIdx.x*32, k0 = blockIdx.y*32;
    int tx = threadIdx.x, ty = threadIdx.y;  // 32 x 8
    #pragma unroll
    for (int i = ty; i < 32; i += 8)
        tile[i][tx] = W[(size_t)(k0+i)*N + n0 + tx];
    __syncthreads();
    #pragma unroll
    for (int i = ty; i < 32; i += 8)
        oh[(size_t)(n0+i)*K + k0 + tx] = __float2half_rn(tile[tx][i]);
}

// ---------------- build initial sequence (R10 style: one block per token) ----------------
__global__ void build_kernel(const float* __restrict__ x,
                             const float* __restrict__ Wnv, const float* __restrict__ bnv,
                             const float* __restrict__ Wv,  const float* __restrict__ bv,
                             float* __restrict__ X, __half* __restrict__ Xh)
{
    int b = blockIdx.x, p = blockIdx.y, t = threadIdx.x;   // 256 threads
    const float* xb = x + (size_t)b*SEQ*EMB;
    size_t oidx = ((size_t)b*SEQ + p)*EMB + t;
    float val;
    if (p == 0 || p == 51) {
        __shared__ float xs[EMB];
        const float* src = xb + (size_t)(p == 0 ? 50 : 101)*EMB;
        const float* W   = (p == 0) ? Wnv : Wv;
        const float* bb  = (p == 0) ? bnv : bv;
        xs[t] = src[t];
        __syncthreads();
        float acc = bb[t];
        #pragma unroll 8
        for (int k = 0; k < EMB; k++) acc = fmaf(xs[k], W[k*EMB + t], acc);
        val = acc;
    } else {
        int srcp = p - 1;
        val = xb[(size_t)srcp*EMB + t];
    }
    X[oidx] = val;
    Xh[oidx] = __float2half_rn(val);
}

// ================= HMMA fp16 GEMM, 128x128 tile, 4-stage cp.async =================
#define PITCH 40
#define A_ST  (128*PITCH)
#define B_ST  (128*PITCH)
#define NSTG  4
#define AB0   (NSTG*A_ST*2)
#define GEMM_SMEM (NSTG*(A_ST + B_ST)*2)  // 81920 bytes

__global__ __launch_bounds__(256, 2) void gemm_mma(
    const __half* __restrict__ Ah, const __half* __restrict__ Bh,
    const float* __restrict__ bias, const float* __restrict__ res,
    float* __restrict__ C, __half* __restrict__ Ch,
    int M, int N, int K, int do_relu)
{
    extern __shared__ __align__(16) __half sm[];
    const uint32_t uBase = smem_u32(sm);

    const int t    = threadIdx.x;
    const int lane = t & 31;
    const int wid  = t >> 5;
    const int wm   = wid & 3;
    const int wn   = wid >> 2;
    const int bm   = blockIdx.y * 128;
    const int bn   = blockIdx.x * 128;

    float acc[2][8][4];
    #pragma unroll
    for (int mt = 0; mt < 2; mt++)
        #pragma unroll
        for (int nt = 0; nt < 8; nt++)
            #pragma unroll
            for (int i = 0; i < 4; i++) acc[mt][nt][i] = 0.f;

    const int nchunks = K >> 5;

    auto load_stage = [&](int ck) {
        const int s  = ck % NSTG;
        const int k0 = ck << 5;
        #pragma unroll
        for (int i = 0; i < 2; i++) {
            int cid = t + i*256;
            int row = cid >> 2;
            int c8  = (cid & 3) << 3;
            cp16(uBase + (uint32_t)((s*128 + row)*PITCH + c8)*2,
                 Ah + (size_t)(bm + row)*K + k0 + c8);
        }
        #pragma unroll
        for (int i = 0; i < 2; i++) {
            int cid = t + i*256;
            int row = cid >> 2;
            int c8  = (cid & 3) << 3;
            cp16(uBase + AB0 + (uint32_t)((s*128 + row)*PITCH + c8)*2,
                 Bh + (size_t)(bn + row)*K + k0 + c8);
        }
    };

    load_stage(0); CP_COMMIT();
    if (nchunks > 1) { load_stage(1); CP_COMMIT(); }
    if (nchunks > 2) { load_stage(2); CP_COMMIT(); }

    for (int ck = 0; ck < nchunks; ck++) {
        CP_WAIT2();
        __syncthreads();
        if (ck + 3 < nchunks) { load_stage(ck + 3); CP_COMMIT(); }
        else { CP_COMMIT(); }

        const int s = ck % NSTG;
        const uint32_t aBase = uBase + (uint32_t)(s*A_ST)*2;
        const uint32_t bBase = uBase + AB0 + (uint32_t)(s*B_ST)*2;

        #pragma unroll
        for (int ks = 0; ks < 2; ks++) {
            uint32_t ah[2][4], bh[8][2];
            const int kcol = ks*16 + ((lane >> 4) << 3);
            #pragma unroll
            for (int mt = 0; mt < 2; mt++) {
                int row = wm*32 + mt*16 + (lane & 15);
                LDSM4(ah[mt], aBase + (uint32_t)(row*PITCH + kcol)*2);
            }
            #pragma unroll
            for (int p = 0; p < 4; p++) {
                int row = wn*64 + p*16 + (lane & 15);
                uint32_t r4[4];
                LDSM4(r4, bBase + (uint32_t)(row*PITCH + kcol)*2);
                bh[2*p][0] = r4[0]; bh[2*p+1][0] = r4[1];
                bh[2*p][1] = r4[2]; bh[2*p+1][1] = r4[3];
            }
            #pragma unroll
            for (int mt = 0; mt < 2; mt++)
                #pragma unroll
                for (int nt = 0; nt < 8; nt++)
                    MMA16816(acc[mt][nt], ah[mt], bh[nt]);
        }
    }

    // ---- epilogue ----
    const int rb = bm + wm*32;
    const int cb = bn + wn*64;
    const int lr = lane >> 2;
    const int lc = (lane & 3) << 1;
    #pragma unroll
    for (int mt = 0; mt < 2; mt++) {
        #pragma unroll
        for (int nt = 0; nt < 8; nt++) {
            int r0 = rb + mt*16 + lr;
            int r1 = r0 + 8;
            int cc = cb + nt*8 + lc;
            float2 v0 = make_float2(acc[mt][nt][0], acc[mt][nt][1]);
            float2 v1 = make_float2(acc[mt][nt][2], acc[mt][nt][3]);
            if (bias) {
                float2 bb = *(const float2*)(bias + cc);
                v0.x += bb.x; v0.y += bb.y; v1.x += bb.x; v1.y += bb.y;
            }
            if (res) {
                float2 q0 = *(const float2*)(res + (size_t)r0*N + cc);
                float2 q1 = *(const float2*)(res + (size_t)r1*N + cc);
                v0.x += q0.x; v0.y += q0.y; v1.x += q1.x; v1.y += q1.y;
            }
            if (do_relu) {
                v0.x = fmaxf(v0.x, 0.f); v0.y = fmaxf(v0.y, 0.f);
                v1.x = fmaxf(v1.x, 0.f); v1.y = fmaxf(v1.y, 0.f);
            }
            if (C) {
                *(float2*)(C + (size_t)r0*N + cc) = v0;
                *(float2*)(C + (size_t)r1*N + cc) = v1;
            }
            if (Ch) {
                *(__half2*)(Ch + (size_t)r0*N + cc) =
                    __halves2half2(__float2half_rn(v0.x), __float2half_rn(v0.y));
                *(__half2*)(Ch + (size_t)r1*N + cc) =
                    __halves2half2(__float2half_rn(v1.x), __float2half_rn(v1.y));
            }
        }
    }
}

// ================= tensor-core flash attention =================
// One block per (batch, head). 4 warps. Q padded to 128 rows (8 m16 tiles,
// 2 per warp); keys padded to 112 (14 n8 tiles / 7 k16 steps).
#define APITCH 24        // halfs per smem row (48B, conflict-free ldmatrix)

__device__ __forceinline__ uint32_t lds_addr(uint32_t base, int row0, int lane) {
    return base + (uint32_t)((row0 + (lane & 15))*(APITCH*2) + ((lane >> 4) << 4));
}

__global__ __launch_bounds__(128, 2) void attn_kernel(
    const __half* __restrict__ QKV, __half* __restrict__ Oh)
{
    const int b = blockIdx.x, h = blockIdx.y, t = threadIdx.x;
    const int lane = t & 31, wid = t >> 5;
    __shared__ __align__(16) __half sQ[128*APITCH];
    __shared__ __align__(16) __half sK[112*APITCH];
    __shared__ __align__(16) __half sV[112*APITCH];

    // zero padded regions (zero everything; cheap)
    for (int i = t; i < 128*APITCH/2; i += 128) ((uint32_t*)sQ)[i] = 0;
    for (int i = t; i < 112*APITCH/2; i += 128) {
        ((uint32_t*)sK)[i] = 0;
        ((uint32_t*)sV)[i] = 0;
    }
    __syncthreads();

    const size_t rowb = (size_t)b*SEQ*QKVW;
    const int hc = h*HD;
    for (int idx = t; idx < SEQ*8; idx += 128) {   // 8 half2 per row of 16
        int n = idx >> 3, j = idx & 7;
        const __half2* base = (const __half2*)(QKV + rowb + (size_t)n*QKVW + hc);
        ((__half2*)sQ)[n*(APITCH/2) + j] = base[j];
        ((__half2*)sK)[n*(APITCH/2) + j] = *((const __half2*)(QKV + rowb + (size_t)n*QKVW + EMB   + hc) + j);
        ((__half2*)sV)[n*(APITCH/2) + j] = *((const __half2*)(QKV + rowb + (size_t)n*QKVW + 2*EMB + hc) + j);
    }
    __syncthreads();

    const uint32_t uQ = smem_u32(sQ);
    const uint32_t uK = smem_u32(sK);
    const uint32_t uV = smem_u32(sV);

    // ---- S = Q K^T ----
    float sc[2][14][4];
    #pragma unroll
    for (int mt = 0; mt < 2; mt++)
        #pragma unroll
        for (int nt = 0; nt < 14; nt++)
            #pragma unroll
            for (int i = 0; i < 4; i++) sc[mt][nt][i] = 0.f;

    uint32_t qa[2][4];
    #pragma unroll
    for (int mt = 0; mt < 2; mt++)
        LDSM4(qa[mt], lds_addr(uQ, wid*32 + mt*16, lane));

    uint32_t kb[14][2];
    #pragma unroll
    for (int p = 0; p < 7; p++) {
        uint32_t r4[4];
        LDSM4(r4, lds_addr(uK, p*16, lane));
        kb[2*p][0]   = r4[0]; kb[2*p][1]   = r4[2];
        kb[2*p+1][0] = r4[1]; kb[2*p+1][1] = r4[3];
    }
    #pragma unroll
    for (int mt = 0; mt < 2; mt++)
        #pragma unroll
        for (int nt = 0; nt < 14; nt++)
            MMA16816(sc[mt][nt], qa[mt], kb[nt]);

    // ---- mask padded keys (cols >= 102) ----
    #pragma unroll
    for (int mt = 0; mt < 2; mt++) {
        if ((lane & 3) == 3) {          // ntile 12 cols 102,103
            sc[mt][12][0] = -1e30f; sc[mt][12][1] = -1e30f;
            sc[mt][12][2] = -1e30f; sc[mt][12][3] = -1e30f;
        }
        #pragma unroll
        for (int i = 0; i < 4; i++) sc[mt][13][i] = -1e30f;
    }

    // ---- softmax (scale 0.25 folded into exp arg) ----
    float invs[2][2];
    #pragma unroll
    for (int mt = 0; mt < 2; mt++) {
        float mxA = -1e30f, mxB = -1e30f;
        #pragma unroll
        for (int nt = 0; nt < 14; nt++) {
            mxA = fmaxf(mxA, fmaxf(sc[mt][nt][0], sc[mt][nt][1]));
            mxB = fmaxf(mxB, fmaxf(sc[mt][nt][2], sc[mt][nt][3]));
        }
        mxA = fmaxf(mxA, __shfl_xor_sync(0xffffffffu, mxA, 1));
        mxA = fmaxf(mxA, __shfl_xor_sync(0xffffffffu, mxA, 2));
        mxB = fmaxf(mxB, __shfl_xor_sync(0xffffffffu, mxB, 1));
        mxB = fmaxf(mxB, __shfl_xor_sync(0xffffffffu, mxB, 2));
        const float nA = -0.25f*mxA, nB = -0.25f*mxB;
        float sA = 0.f, sB = 0.f;
        #pragma unroll
        for (int nt = 0; nt < 14; nt++) {
            float p0 = __expf(fmaf(sc[mt][nt][0], 0.25f, nA));
            float p1 = __expf(fmaf(sc[mt][nt][1], 0.25f, nA));
            float p2 = __expf(fmaf(sc[mt][nt][2], 0.25f, nB));
            float p3 = __expf(fmaf(sc[mt][nt][3], 0.25f, nB));
            sc[mt][nt][0] = p0; sc[mt][nt][1] = p1;
            sc[mt][nt][2] = p2; sc[mt][nt][3] = p3;
            sA += p0 + p1; sB += p2 + p3;
        }
        sA += __shfl_xor_sync(0xffffffffu, sA, 1);
        sA += __shfl_xor_sync(0xffffffffu, sA, 2);
        sB += __shfl_xor_sync(0xffffffffu, sB, 1);
        sB += __shfl_xor_sync(0xffffffffu, sB, 2);
        invs[mt][0] = 1.f/sA;
        invs[mt][1] = 1.f/sB;
    }

    // ---- O = P V ----
    float oc[2][2][4];
    #pragma unroll
    for (int mt = 0; mt < 2; mt++)
        #pragma unroll
        for (int nt = 0; nt < 2; nt++)
            #pragma unroll
            for (int i = 0; i < 4; i++) oc[mt][nt][i] = 0.f;

    #pragma unroll
    for (int ks = 0; ks < 7; ks++) {
        uint32_t r4[4];
        LDSM4T(r4, lds_addr(uV, ks*16, lane));
        uint32_t vb0[2] = { r4[0], r4[1] };
        uint32_t vb1[2] = { r4[2], r4[3] };
        #pragma unroll
        for (int mt = 0; mt < 2; mt++) {
            uint32_t pa[4];
            pa[0] = pack_h2(sc[mt][2*ks  ][0], sc[mt][2*ks  ][1]);
            pa[1] = pack_h2(sc[mt][2*ks  ][2], sc[mt][2*ks  ][3]);
            pa[2] = pack_h2(sc[mt][2*ks+1][0], sc[mt][2*ks+1][1]);
            pa[3] = pack_h2(sc[mt][2*ks+1][2], sc[mt][2*ks+1][3]);
            MMA16816(oc[mt][0], pa, vb0);
            MMA16816(oc[mt][1], pa, vb1);
        }
    }

    // ---- store O (normalized) ----
    #pragma unroll
    for (int mt = 0; mt < 2; mt++) {
        int r0 = wid*32 + mt*16 + (lane >> 2);
        int r1 = r0 + 8;
        #pragma unroll
        for (int nt = 0; nt < 2; nt++) {
            int col = hc + nt*8 + (lane & 3)*2;
            if (r0 < SEQ)
                *(__half2*)(Oh + ((size_t)b*SEQ + r0)*EMB + col) =
                    __floats2half2_rn(oc[mt][nt][0]*invs[mt][0],
                                      oc[mt][nt][1]*invs[mt][0]);
            if (r1 < SEQ)
                *(__half2*)(Oh + ((size_t)b*SEQ + r1)*EMB + col) =
                    __floats2half2_rn(oc[mt][nt][2]*invs[mt][1],
                                      oc[mt][nt][3]*invs[mt][1]);
        }
    }
}

// ---------------- final: logits -> masked softmax -> props -> scatter ----------------
__global__ __launch_bounds__(128) void final_kernel(
    const float* __restrict__ X,  const float* __restrict__ Wf,
    const float* __restrict__ bf, const float* __restrict__ mask,
    const int* __restrict__ lastu, const int* __restrict__ depotu,
    float* __restrict__ out)
{
    int b = blockIdx.x, t = threadIdx.x;   // 128 threads
    __shared__ float lg[128];
    __shared__ float red[128];

    float acc = -INFINITY;
    if (t < SEQ) {
        const float4* r4 = (const float4*)(X + ((size_t)b*SEQ + t)*EMB);
        const float4* w4 = (const float4*)Wf;
        float s = bf[0];
        #pragma unroll 16
        for (int k = 0; k < EMB/4; k++) {
            float4 a = r4[k], w = w4[k];
            s = fmaf(a.x, w.x, s); s = fmaf(a.y, w.y, s);
            s = fmaf(a.z, w.z, s); s = fmaf(a.w, w.w, s);
        }
        if (t >= 1 && t <= KSZ) s += mask[(size_t)b*KSZ + (t-1)];
        if (t == 0 || t == KSZ+1) s = -INFINITY;
        acc = s;
    }
    lg[t] = acc;
    __syncthreads();

    red[t] = lg[t];
    __syncthreads();
    #pragma unroll
    for (int s = 64; s > 0; s >>= 1) {
        if (t < s) red[t] = fmaxf(red[t], red[t+s]);
        __syncthreads();
    }
    float mx = red[0];
    __syncthreads();

    float e = 0.f;
    if (t < SEQ && t != 0 && t != KSZ+1) e = __expf(lg[t] - mx);
    red[t] = e;
    __syncthreads();
    #pragma unroll
    for (int s = 64; s > 0; s >>= 1) {
        if (t < s) red[t] += red[t+s];
        __syncthreads();
    }
    float inv = 1.f / red[0];
    __syncthreads();
    lg[t] = e * inv;
    __syncthreads();

    float* orow = out + (size_t)b*OUTW;
    for (int i = t; i < OUTW; i += 128) orow[i] = 1e-20f;
    __syncthreads();

    if (t < KSZ) {
        float p1 = lg[1 + t];
        float p2 = lg[KSZ + 2 + t];
        if (p1 <= 1e-5f) p1 += 1e-7f;
        if (p2 <= 1e-5f) p2 += 1e-7f;
        orow[lastu[(size_t)b*KSZ + t]] = p1;
        orow[(PSZ + 1) + depotu[(size_t)b*KSZ + t]] = p2;
    }
}

// ---------------- launch ----------------
extern "C" void kernel_launch(void* const* d_in, const int* in_sizes, int n_in,
                              void* d_out, int out_size)
{
    (void)in_sizes; (void)n_in; (void)out_size;
    const float* x    = (const float*)d_in[0];
    const float* mask = (const float*)d_in[1];
    const float* Wnv  = (const float*)d_in[2];
    const float* bnv  = (const float*)d_in[3];
    const float* Wv_  = (const float*)d_in[4];
    const float* bv   = (const float*)d_in[5];
    const float* Wq   = (const float*)d_in[6];
    const float* Wk   = (const float*)d_in[7];
    const float* Wvp  = (const float*)d_in[8];
    const float* Wc   = (const float*)d_in[9];
    const float* bc   = (const float*)d_in[10];
    const float* W1   = (const float*)d_in[11];
    const float* b1   = (const float*)d_in[12];
    const float* W2   = (const float*)d_in[13];
    const float* b2   = (const float*)d_in[14];
    const float* Wf   = (const float*)d_in[15];
    const float* bf   = (const float*)d_in[16];
    const int*  lastu = (const int*)d_in[17];
    const int* depotu = (const int*)d_in[18];

    float *X, *X1;
    __half *QKVh, *Xh, *Oh, *X1h, *Hh, *Wh;
    cudaGetSymbolAddress((void**)&X,    g_X);
    cudaGetSymbolAddress((void**)&X1,   g_X1);
    cudaGetSymbolAddress((void**)&QKVh, g_QKVh);
    cudaGetSymbolAddress((void**)&Xh,   g_Xh);
    cudaGetSymbolAddress((void**)&Oh,   g_Oh);
    cudaGetSymbolAddress((void**)&X1h,  g_X1h);
    cudaGetSymbolAddress((void**)&Hh,   g_Hh);
    cudaGetSymbolAddress((void**)&Wh,   g_Wh);

    cudaFuncSetAttribute(gemm_mma, cudaFuncAttributeMaxDynamicSharedMemorySize,
                         GEMM_SMEM);

    dim3 ct(32, 8);
    dim3 gQKV(QKVW/128, MTOK/128);   // (6, 408)
    dim3 gE  (EMB/128,  MTOK/128);   // (2, 408)
    dim3 gF  (FFD/128,  MTOK/128);   // (8, 408)

    wconv4_kernel<<<dim3(EMB/32, 4*(EMB/32), NLAYER), ct>>>(Wq, Wk, Wvp, Wc, Wh);
    wconv_kernel<<<dim3(FFD/32, EMB/32, NLAYER), ct>>>(W1, Wh + WQKV_SZ + WC_SZ, EMB, FFD, (size_t)EMB*FFD, WL_SZ);
    wconv_kernel<<<dim3(EMB/32, FFD/32, NLAYER), ct>>>(W2, Wh + WQKV_SZ + WC_SZ + W1_SZ, FFD, EMB, (size_t)FFD*EMB, WL_SZ);

    build_kernel<<<dim3(B_SZ, SEQ), 256>>>(x, Wnv, bnv, Wv_, bv, X, Xh);

    for (int l = 0; l < NLAYER; l++) {
        const __half* wh   = Wh + (size_t)l*WL_SZ;
        const __half* wc_h = wh + WQKV_SZ;
        const __half* w1_h = wh + WQKV_SZ + WC_SZ;
        const __half* w2_h = wh + WQKV_SZ + WC_SZ + W1_SZ;
        const float* bcl = bc + (size_t)l*EMB;
        const float* b1l = b1 + (size_t)l*FFD;
        const float* b2l = b2 + (size_t)l*EMB;

        gemm_mma<<<gQKV, 256, GEMM_SMEM>>>(Xh, wh, nullptr, nullptr,
                                           nullptr, QKVh, MTOK, QKVW, EMB, 0);
        attn_kernel<<<dim3(B_SZ, NH), 128>>>(QKVh, Oh);
        gemm_mma<<<gE, 256, GEMM_SMEM>>>(Oh, wc_h, bcl, X,
                                         X1, X1h, MTOK, EMB, EMB, 0);
        gemm_mma<<<gF, 256, GEMM_SMEM>>>(X1h, w1_h, b1l, nullptr,
                                         nullptr, Hh, MTOK, FFD, EMB, 1);
        gemm_mma<<<gE, 256, GEMM_SMEM>>>(Hh, w2_h, b2l, X1,
                                         X, Xh, MTOK, EMB, FFD, 0);
    }

    final_kernel<<<B_SZ, 128>>>(X, Wf, bf, mask, lastu, depotu, (float*)d_out);
}

// round 13
// speedup vs baseline: 1.3716x; 1.0359x over previous
#include <cuda_runtime.h>
#include <cuda_fp16.h>
#include <math.h>
#include <stdint.h>

// ---------------- problem constants ----------------
#define B_SZ   512
#define SEQ    102
#define EMB    256
#define NH     16
#define HD     16
#define FFD    1024
#define NLAYER 3
#define KSZ    50
#define PSZ    1000
#define MTOK   (B_SZ*SEQ)      // 52224 tokens
#define OUTW   ((PSZ+1)*2)     // 2002
#define QKVW   (3*EMB)         // 768

typedef unsigned long long ull;

// ---------------- device scratch (static; no allocs allowed) ----------------
__device__ float  g_X   [MTOK*EMB];
__device__ float  g_X1  [MTOK*EMB];
__device__ __half g_QKVh[MTOK*QKVW];
__device__ __half g_Xh  [MTOK*EMB];
__device__ __half g_Oh  [MTOK*EMB];
__device__ __half g_X1h [MTOK*EMB];
__device__ __half g_Hh  [MTOK*FFD];
#define WQKV_SZ (QKVW*EMB)
#define WC_SZ   (EMB*EMB)
#define W1_SZ   (FFD*EMB)
#define W2_SZ   (EMB*FFD)
#define WL_SZ   (WQKV_SZ + WC_SZ + W1_SZ + W2_SZ)
__device__ __half g_Wh[NLAYER*WL_SZ];

// ---------------- helpers ----------------
__device__ __forceinline__ uint32_t smem_u32(const void* p) {
    uint32_t a;
    asm("{ .reg .u64 t; cvta.to.shared.u64 t, %1; cvt.u32.u64 %0, t; }"
        : "=r"(a) : "l"(p));
    return a;
}
__device__ __forceinline__ void cp16(uint32_t dst, const void* src) {
    asm volatile("cp.async.cg.shared.global [%0], [%1], 16;" :: "r"(dst), "l"(src));
}
#define CP_COMMIT() asm volatile("cp.async.commit_group;" ::: "memory")
#define CP_WAIT1()  asm volatile("cp.async.wait_group 1;" ::: "memory")

#define LDSM4(r, addr) \
    asm volatile("ldmatrix.sync.aligned.m8n8.x4.shared.b16 {%0,%1,%2,%3}, [%4];" \
        : "=r"((r)[0]), "=r"((r)[1]), "=r"((r)[2]), "=r"((r)[3]) : "r"(addr))

#define LDSM4T(r, addr) \
    asm volatile("ldmatrix.sync.aligned.m8n8.x4.trans.shared.b16 {%0,%1,%2,%3}, [%4];" \
        : "=r"((r)[0]), "=r"((r)[1]), "=r"((r)[2]), "=r"((r)[3]) : "r"(addr))

#define MMA16816(d, a, b) \
    asm volatile("mma.sync.aligned.m16n8k16.row.col.f32.f16.f16.f32 " \
        "{%0,%1,%2,%3}, {%4,%5,%6,%7}, {%8,%9}, {%0,%1,%2,%3};" \
        : "+f"((d)[0]), "+f"((d)[1]), "+f"((d)[2]), "+f"((d)[3]) \
        : "r"((a)[0]), "r"((a)[1]), "r"((a)[2]), "r"((a)[3]), \
          "r"((b)[0]), "r"((b)[1]))

__device__ __forceinline__ uint32_t pack_h2(float a, float b) {
    __half2 h = __floats2half2_rn(a, b);
    return *(uint32_t*)&h;
}

// ---------------- weight convert ----------------
__global__ void wconv4_kernel(const float* __restrict__ Wq, const float* __restrict__ Wk,
                              const float* __restrict__ Wv, const float* __restrict__ Wc,
                              __half* __restrict__ oh)
{
    int l   = blockIdx.z;
    int mat = blockIdx.y >> 3;
    int kt  = blockIdx.y & 7;
    const float* W = (mat == 0) ? Wq : (mat == 1) ? Wk : (mat == 2) ? Wv : Wc;
    W  += (size_t)l*EMB*EMB;
    __half* dst = oh + (size_t)l*WL_SZ + (size_t)mat*EMB*EMB;

    __shared__ float tile[32][33];
    int n0 = blockIdx.x*32, k0 = kt*32;
    int tx = threadIdx.x, ty = threadIdx.y;  // 32 x 8
    #pragma unroll
    for (int i = ty; i < 32; i += 8)
        tile[i][tx] = W[(size_t)(k0+i)*EMB + n0 + tx];
    __syncthreads();
    #pragma unroll
    for (int i = ty; i < 32; i += 8)
        dst[(size_t)(n0+i)*EMB + k0 + tx] = __float2half_rn(tile[tx][i]);
}

__global__ void wconv_kernel(const float* __restrict__ W,
                             __half* __restrict__ oh,
                             int K, int N, size_t wstride, size_t ostride)
{
    int l = blockIdx.z;
    W  += (size_t)l*wstride;
    oh += (size_t)l*ostride;
    __shared__ float tile[32][33];
    int n0 = blockIdx.x*32, k0 = blockIdx.y*32;
    int tx = threadIdx.x, ty = threadIdx.y;  // 32 x 8
    #pragma unroll
    for (int i = ty; i < 32; i += 8)
        tile[i][tx] = W[(size_t)(k0+i)*N + n0 + tx];
    __syncthreads();
    #pragma unroll
    for (int i = ty; i < 32; i += 8)
        oh[(size_t)(n0+i)*K + k0 + tx] = __float2half_rn(tile[tx][i]);
}

// ---------------- build initial sequence (one block per token) ----------------
__global__ void build_kernel(const float* __restrict__ x,
                             const float* __restrict__ Wnv, const float* __restrict__ bnv,
                             const float* __restrict__ Wv,  const float* __restrict__ bv,
                             float* __restrict__ X, __half* __restrict__ Xh)
{
    int b = blockIdx.x, p = blockIdx.y, t = threadIdx.x;   // 256 threads
    const float* xb = x + (size_t)b*SEQ*EMB;
    size_t oidx = ((size_t)b*SEQ + p)*EMB + t;
    float val;
    if (p == 0 || p == 51) {
        __shared__ float xs[EMB];
        const float* src = xb + (size_t)(p == 0 ? 50 : 101)*EMB;
        const float* W   = (p == 0) ? Wnv : Wv;
        const float* bb  = (p == 0) ? bnv : bv;
        xs[t] = src[t];
        __syncthreads();
        float acc = bb[t];
        #pragma unroll 8
        for (int k = 0; k < EMB; k++) acc = fmaf(xs[k], W[k*EMB + t], acc);
        val = acc;
    } else {
        int srcp = p - 1;
        val = xb[(size_t)srcp*EMB + t];
    }
    X[oidx] = val;
    Xh[oidx] = __float2half_rn(val);
}

// ================= HMMA fp16 GEMM, 128x128 tile, K-chunk 64, 3-stage =================
#define PITCH 72                          // fp16/row (144B; rows stride 4 banks -> conflict-free LDSM)
#define A_ST  (128*PITCH)                 // 9216 elems per stage
#define B_ST  (128*PITCH)
#define NSTG  3
#define AB0   (NSTG*A_ST*2)               // byte offset of B region (55296)
#define GEMM_SMEM (NSTG*(A_ST + B_ST)*2)  // 110592 bytes

__global__ __launch_bounds__(256, 2) void gemm_mma(
    const __half* __restrict__ Ah, const __half* __restrict__ Bh,
    const float* __restrict__ bias, const float* __restrict__ res,
    float* __restrict__ C, __half* __restrict__ Ch,
    int M, int N, int K, int do_relu)
{
    extern __shared__ __align__(16) __half sm[];
    const uint32_t uBase = smem_u32(sm);

    const int t    = threadIdx.x;
    const int lane = t & 31;
    const int wid  = t >> 5;
    const int wm   = wid & 3;
    const int wn   = wid >> 2;
    const int bm   = blockIdx.y * 128;
    const int bn   = blockIdx.x * 128;

    float acc[2][8][4];
    #pragma unroll
    for (int mt = 0; mt < 2; mt++)
        #pragma unroll
        for (int nt = 0; nt < 8; nt++)
            #pragma unroll
            for (int i = 0; i < 4; i++) acc[mt][nt][i] = 0.f;

    const int nchunks = K >> 6;           // K-chunk 64

    auto load_stage = [&](int ck) {
        const int s  = ck % NSTG;
        const int k0 = ck << 6;
        #pragma unroll
        for (int i = 0; i < 4; i++) {      // A: 1024 16B chunks (128 rows x 64 halfs)
            int cid = t + i*256;
            int row = cid >> 3;
            int c8  = (cid & 7) << 3;
            cp16(uBase + (uint32_t)((s*128 + row)*PITCH + c8)*2,
                 Ah + (size_t)(bm + row)*K + k0 + c8);
        }
        #pragma unroll
        for (int i = 0; i < 4; i++) {      // B: 1024 16B chunks
            int cid = t + i*256;
            int row = cid >> 3;
            int c8  = (cid & 7) << 3;
            cp16(uBase + AB0 + (uint32_t)((s*128 + row)*PITCH + c8)*2,
                 Bh + (size_t)(bn + row)*K + k0 + c8);
        }
    };

    load_stage(0); CP_COMMIT();
    if (nchunks > 1) { load_stage(1); CP_COMMIT(); }

    for (int ck = 0; ck < nchunks; ck++) {
        CP_WAIT1();
        __syncthreads();
        if (ck + 2 < nchunks) { load_stage(ck + 2); CP_COMMIT(); }
        else { CP_COMMIT(); }   // uniform group accounting

        const int s = ck % NSTG;
        const uint32_t aBase = uBase + (uint32_t)(s*A_ST)*2;
        const uint32_t bBase = uBase + AB0 + (uint32_t)(s*B_ST)*2;

        #pragma unroll
        for (int ks = 0; ks < 4; ks++) {
            uint32_t ah[2][4], bh[8][2];
            const int kcol = ks*16 + ((lane >> 4) << 3);
            #pragma unroll
            for (int mt = 0; mt < 2; mt++) {
                int row = wm*32 + mt*16 + (lane & 15);
                LDSM4(ah[mt], aBase + (uint32_t)(row*PITCH + kcol)*2);
            }
            #pragma unroll
            for (int p = 0; p < 4; p++) {
                int row = wn*64 + p*16 + (lane & 15);
                uint32_t r4[4];
                LDSM4(r4, bBase + (uint32_t)(row*PITCH + kcol)*2);
                bh[2*p][0] = r4[0]; bh[2*p+1][0] = r4[1];
                bh[2*p][1] = r4[2]; bh[2*p+1][1] = r4[3];
            }
            #pragma unroll
            for (int mt = 0; mt < 2; mt++)
                #pragma unroll
                for (int nt = 0; nt < 8; nt++)
                    MMA16816(acc[mt][nt], ah[mt], bh[nt]);
        }
        // no bottom sync: top sync of iter ck+1 protects stage (ck-1)%3 reuse
    }

    // ---- epilogue ----
    const int rb = bm + wm*32;
    const int cb = bn + wn*64;
    const int lr = lane >> 2;
    const int lc = (lane & 3) << 1;
    #pragma unroll
    for (int mt = 0; mt < 2; mt++) {
        #pragma unroll
        for (int nt = 0; nt < 8; nt++) {
            int r0 = rb + mt*16 + lr;
            int r1 = r0 + 8;
            int cc = cb + nt*8 + lc;
            float2 v0 = make_float2(acc[mt][nt][0], acc[mt][nt][1]);
            float2 v1 = make_float2(acc[mt][nt][2], acc[mt][nt][3]);
            if (bias) {
                float2 bb = *(const float2*)(bias + cc);
                v0.x += bb.x; v0.y += bb.y; v1.x += bb.x; v1.y += bb.y;
            }
            if (res) {
                float2 q0 = *(const float2*)(res + (size_t)r0*N + cc);
                float2 q1 = *(const float2*)(res + (size_t)r1*N + cc);
                v0.x += q0.x; v0.y += q0.y; v1.x += q1.x; v1.y += q1.y;
            }
            if (do_relu) {
                v0.x = fmaxf(v0.x, 0.f); v0.y = fmaxf(v0.y, 0.f);
                v1.x = fmaxf(v1.x, 0.f); v1.y = fmaxf(v1.y, 0.f);
            }
            if (C) {
                *(float2*)(C + (size_t)r0*N + cc) = v0;
                *(float2*)(C + (size_t)r1*N + cc) = v1;
            }
            if (Ch) {
                *(__half2*)(Ch + (size_t)r0*N + cc) =
                    __halves2half2(__float2half_rn(v0.x), __float2half_rn(v0.y));
                *(__half2*)(Ch + (size_t)r1*N + cc) =
                    __halves2half2(__float2half_rn(v1.x), __float2half_rn(v1.y));
            }
        }
    }
}

// ================= tensor-core flash attention (unchanged from R12) =================
#define APITCH 24

__device__ __forceinline__ uint32_t lds_addr(uint32_t base, int row0, int lane) {
    return base + (uint32_t)((row0 + (lane & 15))*(APITCH*2) + ((lane >> 4) << 4));
}

__global__ __launch_bounds__(128, 2) void attn_kernel(
    const __half* __restrict__ QKV, __half* __restrict__ Oh)
{
    const int b = blockIdx.x, h = blockIdx.y, t = threadIdx.x;
    const int lane = t & 31, wid = t >> 5;
    __shared__ __align__(16) __half sQ[128*APITCH];
    __shared__ __align__(16) __half sK[112*APITCH];
    __shared__ __align__(16) __half sV[112*APITCH];

    for (int i = t; i < 128*APITCH/2; i += 128) ((uint32_t*)sQ)[i] = 0;
    for (int i = t; i < 112*APITCH/2; i += 128) {
        ((uint32_t*)sK)[i] = 0;
        ((uint32_t*)sV)[i] = 0;
    }
    __syncthreads();

    const size_t rowb = (size_t)b*SEQ*QKVW;
    const int hc = h*HD;
    for (int idx = t; idx < SEQ*8; idx += 128) {
        int n = idx >> 3, j = idx & 7;
        const __half2* base = (const __half2*)(QKV + rowb + (size_t)n*QKVW + hc);
        ((__half2*)sQ)[n*(APITCH/2) + j] = base[j];
        ((__half2*)sK)[n*(APITCH/2) + j] = *((const __half2*)(QKV + rowb + (size_t)n*QKVW + EMB   + hc) + j);
        ((__half2*)sV)[n*(APITCH/2) + j] = *((const __half2*)(QKV + rowb + (size_t)n*QKVW + 2*EMB + hc) + j);
    }
    __syncthreads();

    const uint32_t uQ = smem_u32(sQ);
    const uint32_t uK = smem_u32(sK);
    const uint32_t uV = smem_u32(sV);

    float sc[2][14][4];
    #pragma unroll
    for (int mt = 0; mt < 2; mt++)
        #pragma unroll
        for (int nt = 0; nt < 14; nt++)
            #pragma unroll
            for (int i = 0; i < 4; i++) sc[mt][nt][i] = 0.f;

    uint32_t qa[2][4];
    #pragma unroll
    for (int mt = 0; mt < 2; mt++)
        LDSM4(qa[mt], lds_addr(uQ, wid*32 + mt*16, lane));

    uint32_t kb[14][2];
    #pragma unroll
    for (int p = 0; p < 7; p++) {
        uint32_t r4[4];
        LDSM4(r4, lds_addr(uK, p*16, lane));
        kb[2*p][0]   = r4[0]; kb[2*p][1]   = r4[2];
        kb[2*p+1][0] = r4[1]; kb[2*p+1][1] = r4[3];
    }
    #pragma unroll
    for (int mt = 0; mt < 2; mt++)
        #pragma unroll
        for (int nt = 0; nt < 14; nt++)
            MMA16816(sc[mt][nt], qa[mt], kb[nt]);

    #pragma unroll
    for (int mt = 0; mt < 2; mt++) {
        if ((lane & 3) == 3) {
            sc[mt][12][0] = -1e30f; sc[mt][12][1] = -1e30f;
            sc[mt][12][2] = -1e30f; sc[mt][12][3] = -1e30f;
        }
        #pragma unroll
        for (int i = 0; i < 4; i++) sc[mt][13][i] = -1e30f;
    }

    float invs[2][2];
    #pragma unroll
    for (int mt = 0; mt < 2; mt++) {
        float mxA = -1e30f, mxB = -1e30f;
        #pragma unroll
        for (int nt = 0; nt < 14; nt++) {
            mxA = fmaxf(mxA, fmaxf(sc[mt][nt][0], sc[mt][nt][1]));
            mxB = fmaxf(mxB, fmaxf(sc[mt][nt][2], sc[mt][nt][3]));
        }
        mxA = fmaxf(mxA, __shfl_xor_sync(0xffffffffu, mxA, 1));
        mxA = fmaxf(mxA, __shfl_xor_sync(0xffffffffu, mxA, 2));
        mxB = fmaxf(mxB, __shfl_xor_sync(0xffffffffu, mxB, 1));
        mxB = fmaxf(mxB, __shfl_xor_sync(0xffffffffu, mxB, 2));
        const float nA = -0.25f*mxA, nB = -0.25f*mxB;
        float sA = 0.f, sB = 0.f;
        #pragma unroll
        for (int nt = 0; nt < 14; nt++) {
            float p0 = __expf(fmaf(sc[mt][nt][0], 0.25f, nA));
            float p1 = __expf(fmaf(sc[mt][nt][1], 0.25f, nA));
            float p2 = __expf(fmaf(sc[mt][nt][2], 0.25f, nB));
            float p3 = __expf(fmaf(sc[mt][nt][3], 0.25f, nB));
            sc[mt][nt][0] = p0; sc[mt][nt][1] = p1;
            sc[mt][nt][2] = p2; sc[mt][nt][3] = p3;
            sA += p0 + p1; sB += p2 + p3;
        }
        sA += __shfl_xor_sync(0xffffffffu, sA, 1);
        sA += __shfl_xor_sync(0xffffffffu, sA, 2);
        sB += __shfl_xor_sync(0xffffffffu, sB, 1);
        sB += __shfl_xor_sync(0xffffffffu, sB, 2);
        invs[mt][0] = 1.f/sA;
        invs[mt][1] = 1.f/sB;
    }

    float oc[2][2][4];
    #pragma unroll
    for (int mt = 0; mt < 2; mt++)
        #pragma unroll
        for (int nt = 0; nt < 2; nt++)
            #pragma unroll
            for (int i = 0; i < 4; i++) oc[mt][nt][i] = 0.f;

    #pragma unroll
    for (int ks = 0; ks < 7; ks++) {
        uint32_t r4[4];
        LDSM4T(r4, lds_addr(uV, ks*16, lane));
        uint32_t vb0[2] = { r4[0], r4[1] };
        uint32_t vb1[2] = { r4[2], r4[3] };
        #pragma unroll
        for (int mt = 0; mt < 2; mt++) {
            uint32_t pa[4];
            pa[0] = pack_h2(sc[mt][2*ks  ][0], sc[mt][2*ks  ][1]);
            pa[1] = pack_h2(sc[mt][2*ks  ][2], sc[mt][2*ks  ][3]);
            pa[2] = pack_h2(sc[mt][2*ks+1][0], sc[mt][2*ks+1][1]);
            pa[3] = pack_h2(sc[mt][2*ks+1][2], sc[mt][2*ks+1][3]);
            MMA16816(oc[mt][0], pa, vb0);
            MMA16816(oc[mt][1], pa, vb1);
        }
    }

    #pragma unroll
    for (int mt = 0; mt < 2; mt++) {
        int r0 = wid*32 + mt*16 + (lane >> 2);
        int r1 = r0 + 8;
        #pragma unroll
        for (int nt = 0; nt < 2; nt++) {
            int col = hc + nt*8 + (lane & 3)*2;
            if (r0 < SEQ)
                *(__half2*)(Oh + ((size_t)b*SEQ + r0)*EMB + col) =
                    __floats2half2_rn(oc[mt][nt][0]*invs[mt][0],
                                      oc[mt][nt][1]*invs[mt][0]);
            if (r1 < SEQ)
                *(__half2*)(Oh + ((size_t)b*SEQ + r1)*EMB + col) =
                    __floats2half2_rn(oc[mt][nt][2]*invs[mt][1],
                                      oc[mt][nt][3]*invs[mt][1]);
        }
    }
}

// ---------------- final: logits -> masked softmax -> props -> scatter ----------------
__global__ __launch_bounds__(128) void final_kernel(
    const float* __restrict__ X,  const float* __restrict__ Wf,
    const float* __restrict__ bf, const float* __restrict__ mask,
    const int* __restrict__ lastu, const int* __restrict__ depotu,
    float* __restrict__ out)
{
    int b = blockIdx.x, t = threadIdx.x;   // 128 threads
    __shared__ float lg[128];
    __shared__ float red[128];

    float acc = -INFINITY;
    if (t < SEQ) {
        const float4* r4 = (const float4*)(X + ((size_t)b*SEQ + t)*EMB);
        const float4* w4 = (const float4*)Wf;
        float s = bf[0];
        #pragma unroll 16
        for (int k = 0; k < EMB/4; k++) {
            float4 a = r4[k], w = w4[k];
            s = fmaf(a.x, w.x, s); s = fmaf(a.y, w.y, s);
            s = fmaf(a.z, w.z, s); s = fmaf(a.w, w.w, s);
        }
        if (t >= 1 && t <= KSZ) s += mask[(size_t)b*KSZ + (t-1)];
        if (t == 0 || t == KSZ+1) s = -INFINITY;
        acc = s;
    }
    lg[t] = acc;
    __syncthreads();

    red[t] = lg[t];
    __syncthreads();
    #pragma unroll
    for (int s = 64; s > 0; s >>= 1) {
        if (t < s) red[t] = fmaxf(red[t], red[t+s]);
        __syncthreads();
    }
    float mx = red[0];
    __syncthreads();

    float e = 0.f;
    if (t < SEQ && t != 0 && t != KSZ+1) e = __expf(lg[t] - mx);
    red[t] = e;
    __syncthreads();
    #pragma unroll
    for (int s = 64; s > 0; s >>= 1) {
        if (t < s) red[t] += red[t+s];
        __syncthreads();
    }
    float inv = 1.f / red[0];
    __syncthreads();
    lg[t] = e * inv;
    __syncthreads();

    float* orow = out + (size_t)b*OUTW;
    for (int i = t; i < OUTW; i += 128) orow[i] = 1e-20f;
    __syncthreads();

    if (t < KSZ) {
        float p1 = lg[1 + t];
        float p2 = lg[KSZ + 2 + t];
        if (p1 <= 1e-5f) p1 += 1e-7f;
        if (p2 <= 1e-5f) p2 += 1e-7f;
        orow[lastu[(size_t)b*KSZ + t]] = p1;
        orow[(PSZ + 1) + depotu[(size_t)b*KSZ + t]] = p2;
    }
}

// ---------------- launch ----------------
extern "C" void kernel_launch(void* const* d_in, const int* in_sizes, int n_in,
                              void* d_out, int out_size)
{
    (void)in_sizes; (void)n_in; (void)out_size;
    const float* x    = (const float*)d_in[0];
    const float* mask = (const float*)d_in[1];
    const float* Wnv  = (const float*)d_in[2];
    const float* bnv  = (const float*)d_in[3];
    const float* Wv_  = (const float*)d_in[4];
    const float* bv   = (const float*)d_in[5];
    const float* Wq   = (const float*)d_in[6];
    const float* Wk   = (const float*)d_in[7];
    const float* Wvp  = (const float*)d_in[8];
    const float* Wc   = (const float*)d_in[9];
    const float* bc   = (const float*)d_in[10];
    const float* W1   = (const float*)d_in[11];
    const float* b1   = (const float*)d_in[12];
    const float* W2   = (const float*)d_in[13];
    const float* b2   = (const float*)d_in[14];
    const float* Wf   = (const float*)d_in[15];
    const float* bf   = (const float*)d_in[16];
    const int*  lastu = (const int*)d_in[17];
    const int* depotu = (const int*)d_in[18];

    float *X, *X1;
    __half *QKVh, *Xh, *Oh, *X1h, *Hh, *Wh;
    cudaGetSymbolAddress((void**)&X,    g_X);
    cudaGetSymbolAddress((void**)&X1,   g_X1);
    cudaGetSymbolAddress((void**)&QKVh, g_QKVh);
    cudaGetSymbolAddress((void**)&Xh,   g_Xh);
    cudaGetSymbolAddress((void**)&Oh,   g_Oh);
    cudaGetSymbolAddress((void**)&X1h,  g_X1h);
    cudaGetSymbolAddress((void**)&Hh,   g_Hh);
    cudaGetSymbolAddress((void**)&Wh,   g_Wh);

    cudaFuncSetAttribute(gemm_mma, cudaFuncAttributeMaxDynamicSharedMemorySize,
                         GEMM_SMEM);

    dim3 ct(32, 8);
    dim3 gQKV(QKVW/128, MTOK/128);   // (6, 408)
    dim3 gE  (EMB/128,  MTOK/128);   // (2, 408)
    dim3 gF  (FFD/128,  MTOK/128);   // (8, 408)

    wconv4_kernel<<<dim3(EMB/32, 4*(EMB/32), NLAYER), ct>>>(Wq, Wk, Wvp, Wc, Wh);
    wconv_kernel<<<dim3(FFD/32, EMB/32, NLAYER), ct>>>(W1, Wh + WQKV_SZ + WC_SZ, EMB, FFD, (size_t)EMB*FFD, WL_SZ);
    wconv_kernel<<<dim3(EMB/32, FFD/32, NLAYER), ct>>>(W2, Wh + WQKV_SZ + WC_SZ + W1_SZ, FFD, EMB, (size_t)FFD*EMB, WL_SZ);

    build_kernel<<<dim3(B_SZ, SEQ), 256>>>(x, Wnv, bnv, Wv_, bv, X, Xh);

    for (int l = 0; l < NLAYER; l++) {
        const __half* wh   = Wh + (size_t)l*WL_SZ;
        const __half* wc_h = wh + WQKV_SZ;
        const __half* w1_h = wh + WQKV_SZ + WC_SZ;
        const __half* w2_h = wh + WQKV_SZ + WC_SZ + W1_SZ;
        const float* bcl = bc + (size_t)l*EMB;
        const float* b1l = b1 + (size_t)l*FFD;
        const float* b2l = b2 + (size_t)l*EMB;

        gemm_mma<<<gQKV, 256, GEMM_SMEM>>>(Xh, wh, nullptr, nullptr,
                                           nullptr, QKVh, MTOK, QKVW, EMB, 0);
        attn_kernel<<<dim3(B_SZ, NH), 128>>>(QKVh, Oh);
        gemm_mma<<<gE, 256, GEMM_SMEM>>>(Oh, wc_h, bcl, X,
                                         X1, X1h, MTOK, EMB, EMB, 0);
        gemm_mma<<<gF, 256, GEMM_SMEM>>>(X1h, w1_h, b1l, nullptr,
                                         nullptr, Hh, MTOK, FFD, EMB, 1);
        gemm_mma<<<gE, 256, GEMM_SMEM>>>(Hh, w2_h, b2l, X1,
                                         X, Xh, MTOK, EMB, FFD, 0);
    }

    final_kernel<<<B_SZ, 128>>>(X, Wf, bf, mask, lastu, depotu, (float*)d_out);
}

// round 14
// speedup vs baseline: 1.4570x; 1.0623x over previous
#include <cuda_runtime.h>
#include <cuda_fp16.h>
#include <math.h>
#include <stdint.h>

// ---------------- problem constants ----------------
#define B_SZ   512
#define SEQ    102
#define EMB    256
#define NH     16
#define HD     16
#define FFD    1024
#define NLAYER 3
#define KSZ    50
#define PSZ    1000
#define MTOK   (B_SZ*SEQ)      // 52224 tokens
#define OUTW   ((PSZ+1)*2)     // 2002
#define QKVW   (3*EMB)         // 768

typedef unsigned long long ull;

// ---------------- device scratch (static; no allocs allowed) ----------------
__device__ __half g_QKVh[MTOK*QKVW];
__device__ __half g_Xh  [MTOK*EMB];
__device__ __half g_Oh  [MTOK*EMB];
__device__ __half g_X1h [MTOK*EMB];
__device__ __half g_Hh  [MTOK*FFD];
#define WQKV_SZ (QKVW*EMB)
#define WC_SZ   (EMB*EMB)
#define W1_SZ   (FFD*EMB)
#define W2_SZ   (EMB*FFD)
#define WL_SZ   (WQKV_SZ + WC_SZ + W1_SZ + W2_SZ)
__device__ __half g_Wh[NLAYER*WL_SZ];

// ---------------- helpers ----------------
__device__ __forceinline__ uint32_t smem_u32(const void* p) {
    uint32_t a;
    asm("{ .reg .u64 t; cvta.to.shared.u64 t, %1; cvt.u32.u64 %0, t; }"
        : "=r"(a) : "l"(p));
    return a;
}
__device__ __forceinline__ void cp16(uint32_t dst, const void* src) {
    asm volatile("cp.async.cg.shared.global [%0], [%1], 16;" :: "r"(dst), "l"(src));
}
#define CP_COMMIT() asm volatile("cp.async.commit_group;" ::: "memory")
#define CP_WAIT1()  asm volatile("cp.async.wait_group 1;" ::: "memory")

#define LDSM4(r, addr) \
    asm volatile("ldmatrix.sync.aligned.m8n8.x4.shared.b16 {%0,%1,%2,%3}, [%4];" \
        : "=r"((r)[0]), "=r"((r)[1]), "=r"((r)[2]), "=r"((r)[3]) : "r"(addr))

#define LDSM4T(r, addr) \
    asm volatile("ldmatrix.sync.aligned.m8n8.x4.trans.shared.b16 {%0,%1,%2,%3}, [%4];" \
        : "=r"((r)[0]), "=r"((r)[1]), "=r"((r)[2]), "=r"((r)[3]) : "r"(addr))

#define MMA16816(d, a, b) \
    asm volatile("mma.sync.aligned.m16n8k16.row.col.f32.f16.f16.f32 " \
        "{%0,%1,%2,%3}, {%4,%5,%6,%7}, {%8,%9}, {%0,%1,%2,%3};" \
        : "+f"((d)[0]), "+f"((d)[1]), "+f"((d)[2]), "+f"((d)[3]) \
        : "r"((a)[0]), "r"((a)[1]), "r"((a)[2]), "r"((a)[3]), \
          "r"((b)[0]), "r"((b)[1]))

__device__ __forceinline__ uint32_t pack_h2(float a, float b) {
    __half2 h = __floats2half2_rn(a, b);
    return *(uint32_t*)&h;
}

// ---------------- weight convert ----------------
__global__ void wconv4_kernel(const float* __restrict__ Wq, const float* __restrict__ Wk,
                              const float* __restrict__ Wv, const float* __restrict__ Wc,
                              __half* __restrict__ oh)
{
    int l   = blockIdx.z;
    int mat = blockIdx.y >> 3;
    int kt  = blockIdx.y & 7;
    const float* W = (mat == 0) ? Wq : (mat == 1) ? Wk : (mat == 2) ? Wv : Wc;
    W  += (size_t)l*EMB*EMB;
    __half* dst = oh + (size_t)l*WL_SZ + (size_t)mat*EMB*EMB;

    __shared__ float tile[32][33];
    int n0 = blockIdx.x*32, k0 = kt*32;
    int tx = threadIdx.x, ty = threadIdx.y;  // 32 x 8
    #pragma unroll
    for (int i = ty; i < 32; i += 8)
        tile[i][tx] = W[(size_t)(k0+i)*EMB + n0 + tx];
    __syncthreads();
    #pragma unroll
    for (int i = ty; i < 32; i += 8)
        dst[(size_t)(n0+i)*EMB + k0 + tx] = __float2half_rn(tile[tx][i]);
}

__global__ void wconv_kernel(const float* __restrict__ W,
                             __half* __restrict__ oh,
                             int K, int N, size_t wstride, size_t ostride)
{
    int l = blockIdx.z;
    W  += (size_t)l*wstride;
    oh += (size_t)l*ostride;
    __shared__ float tile[32][33];
    int n0 = blockIdx.x*32, k0 = blockIdx.y*32;
    int tx = threadIdx.x, ty = threadIdx.y;  // 32 x 8
    #pragma unroll
    for (int i = ty; i < 32; i += 8)
        tile[i][tx] = W[(size_t)(k0+i)*N + n0 + tx];
    __syncthreads();
    #pragma unroll
    for (int i = ty; i < 32; i += 8)
        oh[(size_t)(n0+i)*K + k0 + tx] = __float2half_rn(tile[tx][i]);
}

// ---------------- build initial sequence (fp16 out only) ----------------
__global__ void build_kernel(const float* __restrict__ x,
                             const float* __restrict__ Wnv, const float* __restrict__ bnv,
                             const float* __restrict__ Wv,  const float* __restrict__ bv,
                             __half* __restrict__ Xh)
{
    int b = blockIdx.x, p = blockIdx.y, t = threadIdx.x;   // 256 threads
    const float* xb = x + (size_t)b*SEQ*EMB;
    size_t oidx = ((size_t)b*SEQ + p)*EMB + t;
    float val;
    if (p == 0 || p == 51) {
        __shared__ float xs[EMB];
        const float* src = xb + (size_t)(p == 0 ? 50 : 101)*EMB;
        const float* W   = (p == 0) ? Wnv : Wv;
        const float* bb  = (p == 0) ? bnv : bv;
        xs[t] = src[t];
        __syncthreads();
        float acc = bb[t];
        #pragma unroll 8
        for (int k = 0; k < EMB; k++) acc = fmaf(xs[k], W[k*EMB + t], acc);
        val = acc;
    } else {
        int srcp = p - 1;
        val = xb[(size_t)srcp*EMB + t];
    }
    Xh[oidx] = __float2half_rn(val);
}

// ================= HMMA fp16 GEMM, 128x128 tile, K-chunk 64, 3-stage =================
// C = A@B^T (+bias fp32) (+res fp16) (relu?) -> fp16 out
#define PITCH 72
#define A_ST  (128*PITCH)
#define B_ST  (128*PITCH)
#define NSTG  3
#define AB0   (NSTG*A_ST*2)
#define GEMM_SMEM (NSTG*(A_ST + B_ST)*2)  // 110592 bytes

__global__ __launch_bounds__(256, 2) void gemm_mma(
    const __half* __restrict__ Ah, const __half* __restrict__ Bh,
    const float* __restrict__ bias, const __half* __restrict__ res,
    __half* __restrict__ Ch,
    int M, int N, int K, int do_relu)
{
    extern __shared__ __align__(16) __half sm[];
    const uint32_t uBase = smem_u32(sm);

    const int t    = threadIdx.x;
    const int lane = t & 31;
    const int wid  = t >> 5;
    const int wm   = wid & 3;
    const int wn   = wid >> 2;
    const int bm   = blockIdx.y * 128;
    const int bn   = blockIdx.x * 128;

    float acc[2][8][4];
    #pragma unroll
    for (int mt = 0; mt < 2; mt++)
        #pragma unroll
        for (int nt = 0; nt < 8; nt++)
            #pragma unroll
            for (int i = 0; i < 4; i++) acc[mt][nt][i] = 0.f;

    const int nchunks = K >> 6;

    auto load_stage = [&](int ck) {
        const int s  = ck % NSTG;
        const int k0 = ck << 6;
        #pragma unroll
        for (int i = 0; i < 4; i++) {
            int cid = t + i*256;
            int row = cid >> 3;
            int c8  = (cid & 7) << 3;
            cp16(uBase + (uint32_t)((s*128 + row)*PITCH + c8)*2,
                 Ah + (size_t)(bm + row)*K + k0 + c8);
        }
        #pragma unroll
        for (int i = 0; i < 4; i++) {
            int cid = t + i*256;
            int row = cid >> 3;
            int c8  = (cid & 7) << 3;
            cp16(uBase + AB0 + (uint32_t)((s*128 + row)*PITCH + c8)*2,
                 Bh + (size_t)(bn + row)*K + k0 + c8);
        }
    };

    load_stage(0); CP_COMMIT();
    if (nchunks > 1) { load_stage(1); CP_COMMIT(); }

    for (int ck = 0; ck < nchunks; ck++) {
        CP_WAIT1();
        __syncthreads();
        if (ck + 2 < nchunks) { load_stage(ck + 2); CP_COMMIT(); }
        else { CP_COMMIT(); }

        const int s = ck % NSTG;
        const uint32_t aBase = uBase + (uint32_t)(s*A_ST)*2;
        const uint32_t bBase = uBase + AB0 + (uint32_t)(s*B_ST)*2;

        #pragma unroll
        for (int ks = 0; ks < 4; ks++) {
            uint32_t ah[2][4], bh[8][2];
            const int kcol = ks*16 + ((lane >> 4) << 3);
            #pragma unroll
            for (int mt = 0; mt < 2; mt++) {
                int row = wm*32 + mt*16 + (lane & 15);
                LDSM4(ah[mt], aBase + (uint32_t)(row*PITCH + kcol)*2);
            }
            #pragma unroll
            for (int p = 0; p < 4; p++) {
                int row = wn*64 + p*16 + (lane & 15);
                uint32_t r4[4];
                LDSM4(r4, bBase + (uint32_t)(row*PITCH + kcol)*2);
                bh[2*p][0] = r4[0]; bh[2*p+1][0] = r4[1];
                bh[2*p][1] = r4[2]; bh[2*p+1][1] = r4[3];
            }
            #pragma unroll
            for (int mt = 0; mt < 2; mt++)
                #pragma unroll
                for (int nt = 0; nt < 8; nt++)
                    MMA16816(acc[mt][nt], ah[mt], bh[nt]);
        }
    }

    // ---- epilogue (all-fp16 out) ----
    const int rb = bm + wm*32;
    const int cb = bn + wn*64;
    const int lr = lane >> 2;
    const int lc = (lane & 3) << 1;
    #pragma unroll
    for (int mt = 0; mt < 2; mt++) {
        #pragma unroll
        for (int nt = 0; nt < 8; nt++) {
            int r0 = rb + mt*16 + lr;
            int r1 = r0 + 8;
            int cc = cb + nt*8 + lc;
            float2 v0 = make_float2(acc[mt][nt][0], acc[mt][nt][1]);
            float2 v1 = make_float2(acc[mt][nt][2], acc[mt][nt][3]);
            if (bias) {
                float2 bb = *(const float2*)(bias + cc);
                v0.x += bb.x; v0.y += bb.y; v1.x += bb.x; v1.y += bb.y;
            }
            if (res) {
                float2 q0 = __half22float2(*(const __half2*)(res + (size_t)r0*N + cc));
                float2 q1 = __half22float2(*(const __half2*)(res + (size_t)r1*N + cc));
                v0.x += q0.x; v0.y += q0.y; v1.x += q1.x; v1.y += q1.y;
            }
            if (do_relu) {
                v0.x = fmaxf(v0.x, 0.f); v0.y = fmaxf(v0.y, 0.f);
                v1.x = fmaxf(v1.x, 0.f); v1.y = fmaxf(v1.y, 0.f);
            }
            *(__half2*)(Ch + (size_t)r0*N + cc) = __floats2half2_rn(v0.x, v0.y);
            *(__half2*)(Ch + (size_t)r1*N + cc) = __floats2half2_rn(v1.x, v1.y);
        }
    }
}

// ================= tensor-core flash attention =================
#define APITCH 24

__device__ __forceinline__ uint32_t lds_addr(uint32_t base, int row0, int lane) {
    return base + (uint32_t)((row0 + (lane & 15))*(APITCH*2) + ((lane >> 4) << 4));
}

__global__ __launch_bounds__(128, 2) void attn_kernel(
    const __half* __restrict__ QKV, __half* __restrict__ Oh)
{
    const int b = blockIdx.x, h = blockIdx.y, t = threadIdx.x;
    const int lane = t & 31, wid = t >> 5;
    __shared__ __align__(16) __half sQ[128*APITCH];
    __shared__ __align__(16) __half sK[112*APITCH];
    __shared__ __align__(16) __half sV[112*APITCH];

    for (int i = t; i < 128*APITCH/2; i += 128) ((uint32_t*)sQ)[i] = 0;
    for (int i = t; i < 112*APITCH/2; i += 128) {
        ((uint32_t*)sK)[i] = 0;
        ((uint32_t*)sV)[i] = 0;
    }
    __syncthreads();

    const size_t rowb = (size_t)b*SEQ*QKVW;
    const int hc = h*HD;
    for (int idx = t; idx < SEQ*8; idx += 128) {
        int n = idx >> 3, j = idx & 7;
        const __half2* base = (const __half2*)(QKV + rowb + (size_t)n*QKVW + hc);
        ((__half2*)sQ)[n*(APITCH/2) + j] = base[j];
        ((__half2*)sK)[n*(APITCH/2) + j] = *((const __half2*)(QKV + rowb + (size_t)n*QKVW + EMB   + hc) + j);
        ((__half2*)sV)[n*(APITCH/2) + j] = *((const __half2*)(QKV + rowb + (size_t)n*QKVW + 2*EMB + hc) + j);
    }
    __syncthreads();

    const uint32_t uQ = smem_u32(sQ);
    const uint32_t uK = smem_u32(sK);
    const uint32_t uV = smem_u32(sV);

    float sc[2][14][4];
    #pragma unroll
    for (int mt = 0; mt < 2; mt++)
        #pragma unroll
        for (int nt = 0; nt < 14; nt++)
            #pragma unroll
            for (int i = 0; i < 4; i++) sc[mt][nt][i] = 0.f;

    uint32_t qa[2][4];
    #pragma unroll
    for (int mt = 0; mt < 2; mt++)
        LDSM4(qa[mt], lds_addr(uQ, wid*32 + mt*16, lane));

    uint32_t kb[14][2];
    #pragma unroll
    for (int p = 0; p < 7; p++) {
        uint32_t r4[4];
        LDSM4(r4, lds_addr(uK, p*16, lane));
        kb[2*p][0]   = r4[0]; kb[2*p][1]   = r4[2];
        kb[2*p+1][0] = r4[1]; kb[2*p+1][1] = r4[3];
    }
    #pragma unroll
    for (int mt = 0; mt < 2; mt++)
        #pragma unroll
        for (int nt = 0; nt < 14; nt++)
            MMA16816(sc[mt][nt], qa[mt], kb[nt]);

    #pragma unroll
    for (int mt = 0; mt < 2; mt++) {
        if ((lane & 3) == 3) {
            sc[mt][12][0] = -1e30f; sc[mt][12][1] = -1e30f;
            sc[mt][12][2] = -1e30f; sc[mt][12][3] = -1e30f;
        }
        #pragma unroll
        for (int i = 0; i < 4; i++) sc[mt][13][i] = -1e30f;
    }

    float invs[2][2];
    #pragma unroll
    for (int mt = 0; mt < 2; mt++) {
        float mxA = -1e30f, mxB = -1e30f;
        #pragma unroll
        for (int nt = 0; nt < 14; nt++) {
            mxA = fmaxf(mxA, fmaxf(sc[mt][nt][0], sc[mt][nt][1]));
            mxB = fmaxf(mxB, fmaxf(sc[mt][nt][2], sc[mt][nt][3]));
        }
        mxA = fmaxf(mxA, __shfl_xor_sync(0xffffffffu, mxA, 1));
        mxA = fmaxf(mxA, __shfl_xor_sync(0xffffffffu, mxA, 2));
        mxB = fmaxf(mxB, __shfl_xor_sync(0xffffffffu, mxB, 1));
        mxB = fmaxf(mxB, __shfl_xor_sync(0xffffffffu, mxB, 2));
        const float nA = -0.25f*mxA, nB = -0.25f*mxB;
        float sA = 0.f, sB = 0.f;
        #pragma unroll
        for (int nt = 0; nt < 14; nt++) {
            float p0 = __expf(fmaf(sc[mt][nt][0], 0.25f, nA));
            float p1 = __expf(fmaf(sc[mt][nt][1], 0.25f, nA));
            float p2 = __expf(fmaf(sc[mt][nt][2], 0.25f, nB));
            float p3 = __expf(fmaf(sc[mt][nt][3], 0.25f, nB));
            sc[mt][nt][0] = p0; sc[mt][nt][1] = p1;
            sc[mt][nt][2] = p2; sc[mt][nt][3] = p3;
            sA += p0 + p1; sB += p2 + p3;
        }
        sA += __shfl_xor_sync(0xffffffffu, sA, 1);
        sA += __shfl_xor_sync(0xffffffffu, sA, 2);
        sB += __shfl_xor_sync(0xffffffffu, sB, 1);
        sB += __shfl_xor_sync(0xffffffffu, sB, 2);
        invs[mt][0] = 1.f/sA;
        invs[mt][1] = 1.f/sB;
    }

    float oc[2][2][4];
    #pragma unroll
    for (int mt = 0; mt < 2; mt++)
        #pragma unroll
        for (int nt = 0; nt < 2; nt++)
            #pragma unroll
            for (int i = 0; i < 4; i++) oc[mt][nt][i] = 0.f;

    #pragma unroll
    for (int ks = 0; ks < 7; ks++) {
        uint32_t r4[4];
        LDSM4T(r4, lds_addr(uV, ks*16, lane));
        uint32_t vb0[2] = { r4[0], r4[1] };
        uint32_t vb1[2] = { r4[2], r4[3] };
        #pragma unroll
        for (int mt = 0; mt < 2; mt++) {
            uint32_t pa[4];
            pa[0] = pack_h2(sc[mt][2*ks  ][0], sc[mt][2*ks  ][1]);
            pa[1] = pack_h2(sc[mt][2*ks  ][2], sc[mt][2*ks  ][3]);
            pa[2] = pack_h2(sc[mt][2*ks+1][0], sc[mt][2*ks+1][1]);
            pa[3] = pack_h2(sc[mt][2*ks+1][2], sc[mt][2*ks+1][3]);
            MMA16816(oc[mt][0], pa, vb0);
            MMA16816(oc[mt][1], pa, vb1);
        }
    }

    #pragma unroll
    for (int mt = 0; mt < 2; mt++) {
        int r0 = wid*32 + mt*16 + (lane >> 2);
        int r1 = r0 + 8;
        #pragma unroll
        for (int nt = 0; nt < 2; nt++) {
            int col = hc + nt*8 + (lane & 3)*2;
            if (r0 < SEQ)
                *(__half2*)(Oh + ((size_t)b*SEQ + r0)*EMB + col) =
                    __floats2half2_rn(oc[mt][nt][0]*invs[mt][0],
                                      oc[mt][nt][1]*invs[mt][0]);
            if (r1 < SEQ)
                *(__half2*)(Oh + ((size_t)b*SEQ + r1)*EMB + col) =
                    __floats2half2_rn(oc[mt][nt][2]*invs[mt][1],
                                      oc[mt][nt][3]*invs[mt][1]);
        }
    }
}

// ---------------- final: logits (fp16 X) -> masked softmax -> scatter ----------------
__global__ __launch_bounds__(128) void final_kernel(
    const __half* __restrict__ Xh,  const float* __restrict__ Wf,
    const float* __restrict__ bf, const float* __restrict__ mask,
    const int* __restrict__ lastu, const int* __restrict__ depotu,
    float* __restrict__ out)
{
    int b = blockIdx.x, t = threadIdx.x;   // 128 threads
    __shared__ float lg[128];
    __shared__ float red[128];

    float acc = -INFINITY;
    if (t < SEQ) {
        const __half2* r2 = (const __half2*)(Xh + ((size_t)b*SEQ + t)*EMB);
        const float2*  w2 = (const float2*)Wf;
        float s = bf[0];
        #pragma unroll 32
        for (int k = 0; k < EMB/2; k++) {
            float2 a = __half22float2(r2[k]);
            float2 w = w2[k];
            s = fmaf(a.x, w.x, s); s = fmaf(a.y, w.y, s);
        }
        if (t >= 1 && t <= KSZ) s += mask[(size_t)b*KSZ + (t-1)];
        if (t == 0 || t == KSZ+1) s = -INFINITY;
        acc = s;
    }
    lg[t] = acc;
    __syncthreads();

    red[t] = lg[t];
    __syncthreads();
    #pragma unroll
    for (int s = 64; s > 0; s >>= 1) {
        if (t < s) red[t] = fmaxf(red[t], red[t+s]);
        __syncthreads();
    }
    float mx = red[0];
    __syncthreads();

    float e = 0.f;
    if (t < SEQ && t != 0 && t != KSZ+1) e = __expf(lg[t] - mx);
    red[t] = e;
    __syncthreads();
    #pragma unroll
    for (int s = 64; s > 0; s >>= 1) {
        if (t < s) red[t] += red[t+s];
        __syncthreads();
    }
    float inv = 1.f / red[0];
    __syncthreads();
    lg[t] = e * inv;
    __syncthreads();

    float* orow = out + (size_t)b*OUTW;
    for (int i = t; i < OUTW; i += 128) orow[i] = 1e-20f;
    __syncthreads();

    if (t < KSZ) {
        float p1 = lg[1 + t];
        float p2 = lg[KSZ + 2 + t];
        if (p1 <= 1e-5f) p1 += 1e-7f;
        if (p2 <= 1e-5f) p2 += 1e-7f;
        orow[lastu[(size_t)b*KSZ + t]] = p1;
        orow[(PSZ + 1) + depotu[(size_t)b*KSZ + t]] = p2;
    }
}

// ---------------- launch ----------------
extern "C" void kernel_launch(void* const* d_in, const int* in_sizes, int n_in,
                              void* d_out, int out_size)
{
    (void)in_sizes; (void)n_in; (void)out_size;
    const float* x    = (const float*)d_in[0];
    const float* mask = (const float*)d_in[1];
    const float* Wnv  = (const float*)d_in[2];
    const float* bnv  = (const float*)d_in[3];
    const float* Wv_  = (const float*)d_in[4];
    const float* bv   = (const float*)d_in[5];
    const float* Wq   = (const float*)d_in[6];
    const float* Wk   = (const float*)d_in[7];
    const float* Wvp  = (const float*)d_in[8];
    const float* Wc   = (const float*)d_in[9];
    const float* bc   = (const float*)d_in[10];
    const float* W1   = (const float*)d_in[11];
    const float* b1   = (const float*)d_in[12];
    const float* W2   = (const float*)d_in[13];
    const float* b2   = (const float*)d_in[14];
    const float* Wf   = (const float*)d_in[15];
    const float* bf   = (const float*)d_in[16];
    const int*  lastu = (const int*)d_in[17];
    const int* depotu = (const int*)d_in[18];

    __half *QKVh, *Xh, *Oh, *X1h, *Hh, *Wh;
    cudaGetSymbolAddress((void**)&QKVh, g_QKVh);
    cudaGetSymbolAddress((void**)&Xh,   g_Xh);
    cudaGetSymbolAddress((void**)&Oh,   g_Oh);
    cudaGetSymbolAddress((void**)&X1h,  g_X1h);
    cudaGetSymbolAddress((void**)&Hh,   g_Hh);
    cudaGetSymbolAddress((void**)&Wh,   g_Wh);

    cudaFuncSetAttribute(gemm_mma, cudaFuncAttributeMaxDynamicSharedMemorySize,
                         GEMM_SMEM);

    dim3 ct(32, 8);
    dim3 gQKV(QKVW/128, MTOK/128);   // (6, 408)
    dim3 gE  (EMB/128,  MTOK/128);   // (2, 408)
    dim3 gF  (FFD/128,  MTOK/128);   // (8, 408)

    wconv4_kernel<<<dim3(EMB/32, 4*(EMB/32), NLAYER), ct>>>(Wq, Wk, Wvp, Wc, Wh);
    wconv_kernel<<<dim3(FFD/32, EMB/32, NLAYER), ct>>>(W1, Wh + WQKV_SZ + WC_SZ, EMB, FFD, (size_t)EMB*FFD, WL_SZ);
    wconv_kernel<<<dim3(EMB/32, FFD/32, NLAYER), ct>>>(W2, Wh + WQKV_SZ + WC_SZ + W1_SZ, FFD, EMB, (size_t)FFD*EMB, WL_SZ);

    build_kernel<<<dim3(B_SZ, SEQ), 256>>>(x, Wnv, bnv, Wv_, bv, Xh);

    for (int l = 0; l < NLAYER; l++) {
        const __half* wh   = Wh + (size_t)l*WL_SZ;
        const __half* wc_h = wh + WQKV_SZ;
        const __half* w1_h = wh + WQKV_SZ + WC_SZ;
        const __half* w2_h = wh + WQKV_SZ + WC_SZ + W1_SZ;
        const float* bcl = bc + (size_t)l*EMB;
        const float* b1l = b1 + (size_t)l*FFD;
        const float* b2l = b2 + (size_t)l*EMB;

        gemm_mma<<<gQKV, 256, GEMM_SMEM>>>(Xh, wh, nullptr, nullptr,
                                           QKVh, MTOK, QKVW, EMB, 0);
        attn_kernel<<<dim3(B_SZ, NH), 128>>>(QKVh, Oh);
        // X1 = X + O@Wc + bc
        gemm_mma<<<gE, 256, GEMM_SMEM>>>(Oh, wc_h, bcl, Xh,
                                         X1h, MTOK, EMB, EMB, 0);
        // H = relu(X1@W1 + b1)
        gemm_mma<<<gF, 256, GEMM_SMEM>>>(X1h, w1_h, b1l, nullptr,
                                         Hh, MTOK, FFD, EMB, 1);
        // X = X1 + H@W2 + b2
        gemm_mma<<<gE, 256, GEMM_SMEM>>>(Hh, w2_h, b2l, X1h,
                                         Xh, MTOK, EMB, FFD, 0);
    }

    final_kernel<<<B_SZ, 128>>>(Xh, Wf, bf, mask, lastu, depotu, (float*)d_out);
}

// round 15
// speedup vs baseline: 1.4725x; 1.0106x over previous
#include <cuda_runtime.h>
#include <cuda_fp16.h>
#include <math.h>
#include <stdint.h>

// ---------------- problem constants ----------------
#define B_SZ   512
#define SEQ    102
#define EMB    256
#define NH     16
#define HD     16
#define FFD    1024
#define NLAYER 3
#define KSZ    50
#define PSZ    1000
#define MTOK   (B_SZ*SEQ)      // 52224 tokens
#define OUTW   ((PSZ+1)*2)     // 2002
#define QKVW   (3*EMB)         // 768

typedef unsigned long long ull;

// ---------------- device scratch (static; no allocs allowed) ----------------
__device__ __half g_QKVh[MTOK*QKVW];
__device__ __half g_Xh  [MTOK*EMB];
__device__ __half g_Oh  [MTOK*EMB];
__device__ __half g_X1h [MTOK*EMB];
__device__ __half g_Hh  [MTOK*FFD];
#define WQKV_SZ (QKVW*EMB)
#define WC_SZ   (EMB*EMB)
#define W1_SZ   (FFD*EMB)
#define W2_SZ   (EMB*FFD)
#define WL_SZ   (WQKV_SZ + WC_SZ + W1_SZ + W2_SZ)
__device__ __half g_Wh[NLAYER*WL_SZ];

// ---------------- helpers ----------------
__device__ __forceinline__ uint32_t smem_u32(const void* p) {
    uint32_t a;
    asm("{ .reg .u64 t; cvta.to.shared.u64 t, %1; cvt.u32.u64 %0, t; }"
        : "=r"(a) : "l"(p));
    return a;
}
__device__ __forceinline__ void cp16(uint32_t dst, const void* src) {
    asm volatile("cp.async.cg.shared.global [%0], [%1], 16;" :: "r"(dst), "l"(src));
}
#define CP_COMMIT() asm volatile("cp.async.commit_group;" ::: "memory")
#define CP_WAIT1()  asm volatile("cp.async.wait_group 1;" ::: "memory")

#define LDSM4(r, addr) \
    asm volatile("ldmatrix.sync.aligned.m8n8.x4.shared.b16 {%0,%1,%2,%3}, [%4];" \
        : "=r"((r)[0]), "=r"((r)[1]), "=r"((r)[2]), "=r"((r)[3]) : "r"(addr))

#define LDSM4T(r, addr) \
    asm volatile("ldmatrix.sync.aligned.m8n8.x4.trans.shared.b16 {%0,%1,%2,%3}, [%4];" \
        : "=r"((r)[0]), "=r"((r)[1]), "=r"((r)[2]), "=r"((r)[3]) : "r"(addr))

#define MMA16816(d, a, b) \
    asm volatile("mma.sync.aligned.m16n8k16.row.col.f32.f16.f16.f32 " \
        "{%0,%1,%2,%3}, {%4,%5,%6,%7}, {%8,%9}, {%0,%1,%2,%3};" \
        : "+f"((d)[0]), "+f"((d)[1]), "+f"((d)[2]), "+f"((d)[3]) \
        : "r"((a)[0]), "r"((a)[1]), "r"((a)[2]), "r"((a)[3]), \
          "r"((b)[0]), "r"((b)[1]))

__device__ __forceinline__ uint32_t pack_h2(float a, float b) {
    __half2 h = __floats2half2_rn(a, b);
    return *(uint32_t*)&h;
}

// ---------------- weight convert ----------------
__global__ void wconv4_kernel(const float* __restrict__ Wq, const float* __restrict__ Wk,
                              const float* __restrict__ Wv, const float* __restrict__ Wc,
                              __half* __restrict__ oh)
{
    int l   = blockIdx.z;
    int mat = blockIdx.y >> 3;
    int kt  = blockIdx.y & 7;
    const float* W = (mat == 0) ? Wq : (mat == 1) ? Wk : (mat == 2) ? Wv : Wc;
    W  += (size_t)l*EMB*EMB;
    __half* dst = oh + (size_t)l*WL_SZ + (size_t)mat*EMB*EMB;

    __shared__ float tile[32][33];
    int n0 = blockIdx.x*32, k0 = kt*32;
    int tx = threadIdx.x, ty = threadIdx.y;  // 32 x 8
    #pragma unroll
    for (int i = ty; i < 32; i += 8)
        tile[i][tx] = W[(size_t)(k0+i)*EMB + n0 + tx];
    __syncthreads();
    #pragma unroll
    for (int i = ty; i < 32; i += 8)
        dst[(size_t)(n0+i)*EMB + k0 + tx] = __float2half_rn(tile[tx][i]);
}

__global__ void wconv_kernel(const float* __restrict__ W,
                             __half* __restrict__ oh,
                             int K, int N, size_t wstride, size_t ostride)
{
    int l = blockIdx.z;
    W  += (size_t)l*wstride;
    oh += (size_t)l*ostride;
    __shared__ float tile[32][33];
    int n0 = blockIdx.x*32, k0 = blockIdx.y*32;
    int tx = threadIdx.x, ty = threadIdx.y;  // 32 x 8
    #pragma unroll
    for (int i = ty; i < 32; i += 8)
        tile[i][tx] = W[(size_t)(k0+i)*N + n0 + tx];
    __syncthreads();
    #pragma unroll
    for (int i = ty; i < 32; i += 8)
        oh[(size_t)(n0+i)*K + k0 + tx] = __float2half_rn(tile[tx][i]);
}

// ---------------- build: copy part (grid-stride, fp32 -> fp16) ----------------
// dst rows 1..50 <- src 0..49 ; dst 52..101 <- src 51..100 (per batch)
__global__ __launch_bounds__(256) void copy_kernel(
    const float* __restrict__ x, __half* __restrict__ Xh)
{
    const int total = B_SZ*100*(EMB/4);   // float4 units
    for (int i = blockIdx.x*256 + threadIdx.x; i < total; i += gridDim.x*256) {
        int c4    = (i & 63) << 2;         // EMB/4 = 64
        int rowid = i >> 6;                // batch*100 + r
        int b = rowid / 100;
        int r = rowid - b*100;
        int src = (r < 50) ? r : r + 1;
        int dst = src + 1;
        const float4 v = *(const float4*)(x + ((size_t)b*SEQ + src)*EMB + c4);
        __half* o = Xh + ((size_t)b*SEQ + dst)*EMB + c4;
        *(__half2*)(o)     = __floats2half2_rn(v.x, v.y);
        *(__half2*)(o + 2) = __floats2half2_rn(v.z, v.w);
    }
}

// ---------------- build: GEMV part (rows 0 and 51 per batch) ----------------
__global__ __launch_bounds__(256) void gemv_kernel(
    const float* __restrict__ x,
    const float* __restrict__ Wnv, const float* __restrict__ bnv,
    const float* __restrict__ Wv,  const float* __restrict__ bv,
    __half* __restrict__ Xh)
{
    int b = blockIdx.x, which = blockIdx.y, t = threadIdx.x;   // 256 threads
    __shared__ float xs[EMB];
    const float* src = x + ((size_t)b*SEQ + (which ? 101 : 50))*EMB;
    const float* W   = which ? Wv : Wnv;
    const float* bb  = which ? bv : bnv;
    xs[t] = src[t];
    __syncthreads();
    float acc = bb[t];
    #pragma unroll 8
    for (int k = 0; k < EMB; k++) acc = fmaf(xs[k], W[k*EMB + t], acc);
    Xh[((size_t)b*SEQ + (which ? 51 : 0))*EMB + t] = __float2half_rn(acc);
}

// ================= HMMA fp16 GEMM, 128x128 tile, K-chunk 64, 3-stage =================
#define PITCH 72
#define A_ST  (128*PITCH)
#define B_ST  (128*PITCH)
#define NSTG  3
#define AB0   (NSTG*A_ST*2)
#define GEMM_SMEM (NSTG*(A_ST + B_ST)*2)  // 110592 bytes

__global__ __launch_bounds__(256, 2) void gemm_mma(
    const __half* __restrict__ Ah, const __half* __restrict__ Bh,
    const float* __restrict__ bias, const __half* __restrict__ res,
    __half* __restrict__ Ch,
    int M, int N, int K, int do_relu)
{
    extern __shared__ __align__(16) __half sm[];
    const uint32_t uBase = smem_u32(sm);

    const int t    = threadIdx.x;
    const int lane = t & 31;
    const int wid  = t >> 5;
    const int wm   = wid & 3;
    const int wn   = wid >> 2;
    const int bm   = blockIdx.y * 128;
    const int bn   = blockIdx.x * 128;

    float acc[2][8][4];
    #pragma unroll
    for (int mt = 0; mt < 2; mt++)
        #pragma unroll
        for (int nt = 0; nt < 8; nt++)
            #pragma unroll
            for (int i = 0; i < 4; i++) acc[mt][nt][i] = 0.f;

    const int nchunks = K >> 6;

    auto load_stage = [&](int ck) {
        const int s  = ck % NSTG;
        const int k0 = ck << 6;
        #pragma unroll
        for (int i = 0; i < 4; i++) {
            int cid = t + i*256;
            int row = cid >> 3;
            int c8  = (cid & 7) << 3;
            cp16(uBase + (uint32_t)((s*128 + row)*PITCH + c8)*2,
                 Ah + (size_t)(bm + row)*K + k0 + c8);
        }
        #pragma unroll
        for (int i = 0; i < 4; i++) {
            int cid = t + i*256;
            int row = cid >> 3;
            int c8  = (cid & 7) << 3;
            cp16(uBase + AB0 + (uint32_t)((s*128 + row)*PITCH + c8)*2,
                 Bh + (size_t)(bn + row)*K + k0 + c8);
        }
    };

    load_stage(0); CP_COMMIT();
    if (nchunks > 1) { load_stage(1); CP_COMMIT(); }

    for (int ck = 0; ck < nchunks; ck++) {
        CP_WAIT1();
        __syncthreads();
        if (ck + 2 < nchunks) { load_stage(ck + 2); CP_COMMIT(); }
        else { CP_COMMIT(); }   // empty groups keep wait_group accounting correct

        const int s = ck % NSTG;
        const uint32_t aBase = uBase + (uint32_t)(s*A_ST)*2;
        const uint32_t bBase = uBase + AB0 + (uint32_t)(s*B_ST)*2;

        #pragma unroll
        for (int ks = 0; ks < 4; ks++) {
            uint32_t ah[2][4], bh[8][2];
            const int kcol = ks*16 + ((lane >> 4) << 3);
            #pragma unroll
            for (int mt = 0; mt < 2; mt++) {
                int row = wm*32 + mt*16 + (lane & 15);
                LDSM4(ah[mt], aBase + (uint32_t)(row*PITCH + kcol)*2);
            }
            #pragma unroll
            for (int p = 0; p < 4; p++) {
                int row = wn*64 + p*16 + (lane & 15);
                uint32_t r4[4];
                LDSM4(r4, bBase + (uint32_t)(row*PITCH + kcol)*2);
                bh[2*p][0] = r4[0]; bh[2*p+1][0] = r4[1];
                bh[2*p][1] = r4[2]; bh[2*p+1][1] = r4[3];
            }
            #pragma unroll
            for (int mt = 0; mt < 2; mt++)
                #pragma unroll
                for (int nt = 0; nt < 8; nt++)
                    MMA16816(acc[mt][nt], ah[mt], bh[nt]);
        }
    }

    // ---- epilogue (all-fp16 out) ----
    const int rb = bm + wm*32;
    const int cb = bn + wn*64;
    const int lr = lane >> 2;
    const int lc = (lane & 3) << 1;
    #pragma unroll
    for (int mt = 0; mt < 2; mt++) {
        #pragma unroll
        for (int nt = 0; nt < 8; nt++) {
            int r0 = rb + mt*16 + lr;
            int r1 = r0 + 8;
            int cc = cb + nt*8 + lc;
            float2 v0 = make_float2(acc[mt][nt][0], acc[mt][nt][1]);
            float2 v1 = make_float2(acc[mt][nt][2], acc[mt][nt][3]);
            if (bias) {
                float2 bb = *(const float2*)(bias + cc);
                v0.x += bb.x; v0.y += bb.y; v1.x += bb.x; v1.y += bb.y;
            }
            if (res) {
                float2 q0 = __half22float2(*(const __half2*)(res + (size_t)r0*N + cc));
                float2 q1 = __half22float2(*(const __half2*)(res + (size_t)r1*N + cc));
                v0.x += q0.x; v0.y += q0.y; v1.x += q1.x; v1.y += q1.y;
            }
            if (do_relu) {
                v0.x = fmaxf(v0.x, 0.f); v0.y = fmaxf(v0.y, 0.f);
                v1.x = fmaxf(v1.x, 0.f); v1.y = fmaxf(v1.y, 0.f);
            }
            *(__half2*)(Ch + (size_t)r0*N + cc) = __floats2half2_rn(v0.x, v0.y);
            *(__half2*)(Ch + (size_t)r1*N + cc) = __floats2half2_rn(v1.x, v1.y);
        }
    }
}

// ================= tensor-core flash attention =================
#define APITCH 24

__device__ __forceinline__ uint32_t lds_addr(uint32_t base, int row0, int lane) {
    return base + (uint32_t)((row0 + (lane & 15))*(APITCH*2) + ((lane >> 4) << 4));
}

__global__ __launch_bounds__(128, 2) void attn_kernel(
    const __half* __restrict__ QKV, __half* __restrict__ Oh)
{
    const int b = blockIdx.x, h = blockIdx.y, t = threadIdx.x;
    const int lane = t & 31, wid = t >> 5;
    __shared__ __align__(16) __half sQ[128*APITCH];
    __shared__ __align__(16) __half sK[112*APITCH];
    __shared__ __align__(16) __half sV[112*APITCH];

    for (int i = t; i < 128*APITCH/2; i += 128) ((uint32_t*)sQ)[i] = 0;
    for (int i = t; i < 112*APITCH/2; i += 128) {
        ((uint32_t*)sK)[i] = 0;
        ((uint32_t*)sV)[i] = 0;
    }
    __syncthreads();

    const size_t rowb = (size_t)b*SEQ*QKVW;
    const int hc = h*HD;
    for (int idx = t; idx < SEQ*8; idx += 128) {
        int n = idx >> 3, j = idx & 7;
        const __half2* base = (const __half2*)(QKV + rowb + (size_t)n*QKVW + hc);
        ((__half2*)sQ)[n*(APITCH/2) + j] = base[j];
        ((__half2*)sK)[n*(APITCH/2) + j] = *((const __half2*)(QKV + rowb + (size_t)n*QKVW + EMB   + hc) + j);
        ((__half2*)sV)[n*(APITCH/2) + j] = *((const __half2*)(QKV + rowb + (size_t)n*QKVW + 2*EMB + hc) + j);
    }
    __syncthreads();

    const uint32_t uQ = smem_u32(sQ);
    const uint32_t uK = smem_u32(sK);
    const uint32_t uV = smem_u32(sV);

    float sc[2][14][4];
    #pragma unroll
    for (int mt = 0; mt < 2; mt++)
        #pragma unroll
        for (int nt = 0; nt < 14; nt++)
            #pragma unroll
            for (int i = 0; i < 4; i++) sc[mt][nt][i] = 0.f;

    uint32_t qa[2][4];
    #pragma unroll
    for (int mt = 0; mt < 2; mt++)
        LDSM4(qa[mt], lds_addr(uQ, wid*32 + mt*16, lane));

    uint32_t kb[14][2];
    #pragma unroll
    for (int p = 0; p < 7; p++) {
        uint32_t r4[4];
        LDSM4(r4, lds_addr(uK, p*16, lane));
        kb[2*p][0]   = r4[0]; kb[2*p][1]   = r4[2];
        kb[2*p+1][0] = r4[1]; kb[2*p+1][1] = r4[3];
    }
    #pragma unroll
    for (int mt = 0; mt < 2; mt++)
        #pragma unroll
        for (int nt = 0; nt < 14; nt++)
            MMA16816(sc[mt][nt], qa[mt], kb[nt]);

    #pragma unroll
    for (int mt = 0; mt < 2; mt++) {
        if ((lane & 3) == 3) {
            sc[mt][12][0] = -1e30f; sc[mt][12][1] = -1e30f;
            sc[mt][12][2] = -1e30f; sc[mt][12][3] = -1e30f;
        }
        #pragma unroll
        for (int i = 0; i < 4; i++) sc[mt][13][i] = -1e30f;
    }

    float invs[2][2];
    #pragma unroll
    for (int mt = 0; mt < 2; mt++) {
        float mxA = -1e30f, mxB = -1e30f;
        #pragma unroll
        for (int nt = 0; nt < 14; nt++) {
            mxA = fmaxf(mxA, fmaxf(sc[mt][nt][0], sc[mt][nt][1]));
            mxB = fmaxf(mxB, fmaxf(sc[mt][nt][2], sc[mt][nt][3]));
        }
        mxA = fmaxf(mxA, __shfl_xor_sync(0xffffffffu, mxA, 1));
        mxA = fmaxf(mxA, __shfl_xor_sync(0xffffffffu, mxA, 2));
        mxB = fmaxf(mxB, __shfl_xor_sync(0xffffffffu, mxB, 1));
        mxB = fmaxf(mxB, __shfl_xor_sync(0xffffffffu, mxB, 2));
        const float nA = -0.25f*mxA, nB = -0.25f*mxB;
        float sA = 0.f, sB = 0.f;
        #pragma unroll
        for (int nt = 0; nt < 14; nt++) {
            float p0 = __expf(fmaf(sc[mt][nt][0], 0.25f, nA));
            float p1 = __expf(fmaf(sc[mt][nt][1], 0.25f, nA));
            float p2 = __expf(fmaf(sc[mt][nt][2], 0.25f, nB));
            float p3 = __expf(fmaf(sc[mt][nt][3], 0.25f, nB));
            sc[mt][nt][0] = p0; sc[mt][nt][1] = p1;
            sc[mt][nt][2] = p2; sc[mt][nt][3] = p3;
            sA += p0 + p1; sB += p2 + p3;
        }
        sA += __shfl_xor_sync(0xffffffffu, sA, 1);
        sA += __shfl_xor_sync(0xffffffffu, sA, 2);
        sB += __shfl_xor_sync(0xffffffffu, sB, 1);
        sB += __shfl_xor_sync(0xffffffffu, sB, 2);
        invs[mt][0] = 1.f/sA;
        invs[mt][1] = 1.f/sB;
    }

    float oc[2][2][4];
    #pragma unroll
    for (int mt = 0; mt < 2; mt++)
        #pragma unroll
        for (int nt = 0; nt < 2; nt++)
            #pragma unroll
            for (int i = 0; i < 4; i++) oc[mt][nt][i] = 0.f;

    #pragma unroll
    for (int ks = 0; ks < 7; ks++) {
        uint32_t r4[4];
        LDSM4T(r4, lds_addr(uV, ks*16, lane));
        uint32_t vb0[2] = { r4[0], r4[1] };
        uint32_t vb1[2] = { r4[2], r4[3] };
        #pragma unroll
        for (int mt = 0; mt < 2; mt++) {
            uint32_t pa[4];
            pa[0] = pack_h2(sc[mt][2*ks  ][0], sc[mt][2*ks  ][1]);
            pa[1] = pack_h2(sc[mt][2*ks  ][2], sc[mt][2*ks  ][3]);
            pa[2] = pack_h2(sc[mt][2*ks+1][0], sc[mt][2*ks+1][1]);
            pa[3] = pack_h2(sc[mt][2*ks+1][2], sc[mt][2*ks+1][3]);
            MMA16816(oc[mt][0], pa, vb0);
            MMA16816(oc[mt][1], pa, vb1);
        }
    }

    #pragma unroll
    for (int mt = 0; mt < 2; mt++) {
        int r0 = wid*32 + mt*16 + (lane >> 2);
        int r1 = r0 + 8;
        #pragma unroll
        for (int nt = 0; nt < 2; nt++) {
            int col = hc + nt*8 + (lane & 3)*2;
            if (r0 < SEQ)
                *(__half2*)(Oh + ((size_t)b*SEQ + r0)*EMB + col) =
                    __floats2half2_rn(oc[mt][nt][0]*invs[mt][0],
                                      oc[mt][nt][1]*invs[mt][0]);
            if (r1 < SEQ)
                *(__half2*)(Oh + ((size_t)b*SEQ + r1)*EMB + col) =
                    __floats2half2_rn(oc[mt][nt][2]*invs[mt][1],
                                      oc[mt][nt][3]*invs[mt][1]);
        }
    }
}

// ---------------- final: logits (fp16 X) -> masked softmax -> scatter ----------------
__global__ __launch_bounds__(128) void final_kernel(
    const __half* __restrict__ Xh,  const float* __restrict__ Wf,
    const float* __restrict__ bf, const float* __restrict__ mask,
    const int* __restrict__ lastu, const int* __restrict__ depotu,
    float* __restrict__ out)
{
    int b = blockIdx.x, t = threadIdx.x;   // 128 threads
    __shared__ float lg[128];
    __shared__ float red[128];

    float acc = -INFINITY;
    if (t < SEQ) {
        const __half2* r2 = (const __half2*)(Xh + ((size_t)b*SEQ + t)*EMB);
        const float2*  w2 = (const float2*)Wf;
        float s = bf[0];
        #pragma unroll 32
        for (int k = 0; k < EMB/2; k++) {
            float2 a = __half22float2(r2[k]);
            float2 w = w2[k];
            s = fmaf(a.x, w.x, s); s = fmaf(a.y, w.y, s);
        }
        if (t >= 1 && t <= KSZ) s += mask[(size_t)b*KSZ + (t-1)];
        if (t == 0 || t == KSZ+1) s = -INFINITY;
        acc = s;
    }
    lg[t] = acc;
    __syncthreads();

    red[t] = lg[t];
    __syncthreads();
    #pragma unroll
    for (int s = 64; s > 0; s >>= 1) {
        if (t < s) red[t] = fmaxf(red[t], red[t+s]);
        __syncthreads();
    }
    float mx = red[0];
    __syncthreads();

    float e = 0.f;
    if (t < SEQ && t != 0 && t != KSZ+1) e = __expf(lg[t] - mx);
    red[t] = e;
    __syncthreads();
    #pragma unroll
    for (int s = 64; s > 0; s >>= 1) {
        if (t < s) red[t] += red[t+s];
        __syncthreads();
    }
    float inv = 1.f / red[0];
    __syncthreads();
    lg[t] = e * inv;
    __syncthreads();

    float* orow = out + (size_t)b*OUTW;
    for (int i = t; i < OUTW; i += 128) orow[i] = 1e-20f;
    __syncthreads();

    if (t < KSZ) {
        float p1 = lg[1 + t];
        float p2 = lg[KSZ + 2 + t];
        if (p1 <= 1e-5f) p1 += 1e-7f;
        if (p2 <= 1e-5f) p2 += 1e-7f;
        orow[lastu[(size_t)b*KSZ + t]] = p1;
        orow[(PSZ + 1) + depotu[(size_t)b*KSZ + t]] = p2;
    }
}

// ---------------- launch ----------------
extern "C" void kernel_launch(void* const* d_in, const int* in_sizes, int n_in,
                              void* d_out, int out_size)
{
    (void)in_sizes; (void)n_in; (void)out_size;
    const float* x    = (const float*)d_in[0];
    const float* mask = (const float*)d_in[1];
    const float* Wnv  = (const float*)d_in[2];
    const float* bnv  = (const float*)d_in[3];
    const float* Wv_  = (const float*)d_in[4];
    const float* bv   = (const float*)d_in[5];
    const float* Wq   = (const float*)d_in[6];
    const float* Wk   = (const float*)d_in[7];
    const float* Wvp  = (const float*)d_in[8];
    const float* Wc   = (const float*)d_in[9];
    const float* bc   = (const float*)d_in[10];
    const float* W1   = (const float*)d_in[11];
    const float* b1   = (const float*)d_in[12];
    const float* W2   = (const float*)d_in[13];
    const float* b2   = (const float*)d_in[14];
    const float* Wf   = (const float*)d_in[15];
    const float* bf   = (const float*)d_in[16];
    const int*  lastu = (const int*)d_in[17];
    const int* depotu = (const int*)d_in[18];

    __half *QKVh, *Xh, *Oh, *X1h, *Hh, *Wh;
    cudaGetSymbolAddress((void**)&QKVh, g_QKVh);
    cudaGetSymbolAddress((void**)&Xh,   g_Xh);
    cudaGetSymbolAddress((void**)&Oh,   g_Oh);
    cudaGetSymbolAddress((void**)&X1h,  g_X1h);
    cudaGetSymbolAddress((void**)&Hh,   g_Hh);
    cudaGetSymbolAddress((void**)&Wh,   g_Wh);

    cudaFuncSetAttribute(gemm_mma, cudaFuncAttributeMaxDynamicSharedMemorySize,
                         GEMM_SMEM);

    dim3 ct(32, 8);
    dim3 gQKV(QKVW/128, MTOK/128);   // (6, 408)
    dim3 gE  (EMB/128,  MTOK/128);   // (2, 408)
    dim3 gF  (FFD/128,  MTOK/128);   // (8, 408)

    wconv4_kernel<<<dim3(EMB/32, 4*(EMB/32), NLAYER), ct>>>(Wq, Wk, Wvp, Wc, Wh);
    wconv_kernel<<<dim3(FFD/32, EMB/32, NLAYER), ct>>>(W1, Wh + WQKV_SZ + WC_SZ, EMB, FFD, (size_t)EMB*FFD, WL_SZ);
    wconv_kernel<<<dim3(EMB/32, FFD/32, NLAYER), ct>>>(W2, Wh + WQKV_SZ + WC_SZ + W1_SZ, FFD, EMB, (size_t)FFD*EMB, WL_SZ);

    copy_kernel<<<4096, 256>>>(x, Xh);
    gemv_kernel<<<dim3(B_SZ, 2), 256>>>(x, Wnv, bnv, Wv_, bv, Xh);

    for (int l = 0; l < NLAYER; l++) {
        const __half* wh   = Wh + (size_t)l*WL_SZ;
        const __half* wc_h = wh + WQKV_SZ;
        const __half* w1_h = wh + WQKV_SZ + WC_SZ;
        const __half* w2_h = wh + WQKV_SZ + WC_SZ + W1_SZ;
        const float* bcl = bc + (size_t)l*EMB;
        const float* b1l = b1 + (size_t)l*FFD;
        const float* b2l = b2 + (size_t)l*EMB;

        gemm_mma<<<gQKV, 256, GEMM_SMEM>>>(Xh, wh, nullptr, nullptr,
                                           QKVh, MTOK, QKVW, EMB, 0);
        attn_kernel<<<dim3(B_SZ, NH), 128>>>(QKVh, Oh);
        gemm_mma<<<gE, 256, GEMM_SMEM>>>(Oh, wc_h, bcl, Xh,
                                         X1h, MTOK, EMB, EMB, 0);
        gemm_mma<<<gF, 256, GEMM_SMEM>>>(X1h, w1_h, b1l, nullptr,
                                         Hh, MTOK, FFD, EMB, 1);
        gemm_mma<<<gE, 256, GEMM_SMEM>>>(Hh, w2_h, b2l, X1h,
                                         Xh, MTOK, EMB, FFD, 0);
    }

    final_kernel<<<B_SZ, 128>>>(Xh, Wf, bf, mask, lastu, depotu, (float*)d_out);
}